// round 1
// baseline (speedup 1.0000x reference)
#include <cuda_runtime.h>
#include <math.h>

// ---------------- problem constants (shapes fixed by the dataset) -----------
#define NNODE 19200      // G * NPG
#define NEDGE 230400     // E (excl self loops)
#define NGRAPH 128
#define LATENT 256
#define FEAT 64
#define HEADS 4
#define POS 180
#define IN1 244          // FEAT + POS
#define DMODEL 256       // HEADS * FEAT
#define ETOT (NEDGE + NNODE)

// ---------------- static device scratch (no runtime allocation) -------------
__device__ __align__(16) float g_bufA[NNODE * DMODEL];   // node features / aggregation out
__device__ __align__(16) float g_bufB[NNODE * DMODEL];   // h = x @ W
__device__ __align__(16) float g_as[NNODE * HEADS];
__device__ __align__(16) float g_ad[NNODE * HEADS];
__device__ __align__(16) float g_m[NNODE * HEADS];
__device__ __align__(16) float g_s[NNODE * HEADS];
__device__ __align__(16) float g_e[ETOT * HEADS];
__device__ __align__(16) float g_x0[NGRAPH * FEAT];
__device__ int g_starts[NGRAPH];

// ---------------- helpers ----------------------------------------------------
__device__ __forceinline__ void atomicMaxF(float* addr, float v) {
    // order-preserving trick: int atomicMax for v>=0, unsigned atomicMin for v<0
    if (v >= 0.0f) atomicMax((int*)addr, __float_as_int(v));
    else           atomicMin((unsigned int*)addr, __float_as_uint(v));
}

// ---------------- kernels ----------------------------------------------------

// x0 = z @ W0 + b0   [G,64]
__global__ void k_x0(const float* __restrict__ z, const float* __restrict__ W0,
                     const float* __restrict__ b0, float* __restrict__ x0) {
    int g = blockIdx.x;
    int c = threadIdx.x;               // 0..63
    float acc = b0[c];
    const float* zr = z + g * LATENT;
    #pragma unroll 4
    for (int k = 0; k < LATENT; k++) acc += zr[k] * W0[k * FEAT + c];
    x0[g * FEAT + c] = acc;
}

// starts[g] = first node index of graph g (batch is sorted)
__global__ void k_starts(const int* __restrict__ batch, int* __restrict__ starts, int N) {
    int i = blockIdx.x * blockDim.x + threadIdx.x;
    if (i >= N) return;
    int b = batch[i];
    if (i == 0 || batch[i - 1] != b) starts[b] = i;
}

// X[N,256] = relu(concat(x0[batch], one_hot(order,180))), cols 244..255 = 0
__global__ void k_build(const float* __restrict__ x0, const int* __restrict__ batch,
                        const int* __restrict__ starts, float* __restrict__ X, int N) {
    int idx = blockIdx.x * blockDim.x + threadIdx.x;
    if (idx >= N * DMODEL) return;
    int node = idx >> 8, c = idx & 255;
    int g = batch[node];
    float v = 0.0f;
    if (c < FEAT) {
        v = x0[g * FEAT + c];
        v = v > 0.0f ? v : 0.0f;
    } else if (c < IN1) {
        int order = node - starts[g];
        v = (order == c - FEAT) ? 1.0f : 0.0f;
    }
    X[idx] = v;
}

// Tiled fp32 GEMM: C[N,256] = X[N,(Kin)] @ W[Kin,256]. X row stride 256 always.
#define BM 64
#define BN 64
#define BK 32
__global__ void k_gemm(const float* __restrict__ X, const float* __restrict__ W,
                       float* __restrict__ C, int Nrows, int Kin) {
    __shared__ float As[BM][BK + 1];
    __shared__ float Bs[BK][BN];
    int tid = threadIdx.x;             // 256 threads
    int tx = tid & 15, ty = tid >> 4;  // 16x16
    int r0 = blockIdx.x * BM;
    int c0 = blockIdx.y * BN;
    float acc[4][4] = {};
    int ktiles = (Kin + BK - 1) / BK;
    for (int kt = 0; kt < ktiles; kt++) {
        int k0 = kt * BK;
        #pragma unroll
        for (int t = 0; t < 8; t++) {
            int idx = tid + t * 256;
            int row = idx >> 5, k = idx & 31;
            float v = 0.0f;
            if (k0 + k < Kin && r0 + row < Nrows) v = X[(r0 + row) * DMODEL + k0 + k];
            As[row][k] = v;
        }
        #pragma unroll
        for (int t = 0; t < 8; t++) {
            int idx = tid + t * 256;
            int k = idx >> 6, col = idx & 63;
            float v = 0.0f;
            if (k0 + k < Kin) v = W[(k0 + k) * DMODEL + c0 + col];
            Bs[k][col] = v;
        }
        __syncthreads();
        #pragma unroll
        for (int k = 0; k < BK; k++) {
            float a0 = As[ty * 4 + 0][k];
            float a1 = As[ty * 4 + 1][k];
            float a2 = As[ty * 4 + 2][k];
            float a3 = As[ty * 4 + 3][k];
            float4 b = *(const float4*)&Bs[k][tx * 4];
            acc[0][0] += a0 * b.x; acc[0][1] += a0 * b.y; acc[0][2] += a0 * b.z; acc[0][3] += a0 * b.w;
            acc[1][0] += a1 * b.x; acc[1][1] += a1 * b.y; acc[1][2] += a1 * b.z; acc[1][3] += a1 * b.w;
            acc[2][0] += a2 * b.x; acc[2][1] += a2 * b.y; acc[2][2] += a2 * b.z; acc[2][3] += a2 * b.w;
            acc[3][0] += a3 * b.x; acc[3][1] += a3 * b.y; acc[3][2] += a3 * b.z; acc[3][3] += a3 * b.w;
        }
        __syncthreads();
    }
    #pragma unroll
    for (int i = 0; i < 4; i++) {
        int r = r0 + ty * 4 + i;
        if (r >= Nrows) continue;
        #pragma unroll
        for (int j = 0; j < 4; j++)
            C[r * DMODEL + c0 + tx * 4 + j] = acc[i][j];
    }
}

// zero aggregation output; init m = -inf, s = 0
__global__ void k_init(float* __restrict__ out, float* __restrict__ m,
                       float* __restrict__ s, int N) {
    int idx = blockIdx.x * blockDim.x + threadIdx.x;
    if (idx >= N * DMODEL) return;
    out[idx] = 0.0f;
    if (idx < N * HEADS) {
        m[idx] = __int_as_float(0xff800000);  // -inf
        s[idx] = 0.0f;
    }
}

// a_s[n,h] = dot(h[n,h,:], att_s[h]), same for a_d.  One warp per node.
__global__ void k_attn(const float* __restrict__ H, const float* __restrict__ attS,
                       const float* __restrict__ attD, float* __restrict__ aS,
                       float* __restrict__ aD, int N) {
    __shared__ float sS[DMODEL], sD[DMODEL];
    int tid = threadIdx.x;
    if (tid < DMODEL) { sS[tid] = attS[tid]; sD[tid] = attD[tid]; }
    __syncthreads();
    int warp = (blockIdx.x * blockDim.x + tid) >> 5;
    int lane = tid & 31;
    if (warp >= N) return;
    const float* hr = H + warp * DMODEL;
    float accS[4] = {0, 0, 0, 0}, accD[4] = {0, 0, 0, 0};
    #pragma unroll
    for (int c = 0; c < 8; c++) {
        int p = c * 32 + lane;
        float hv = hr[p];
        accS[c >> 1] += hv * sS[p];
        accD[c >> 1] += hv * sD[p];
    }
    #pragma unroll
    for (int h = 0; h < 4; h++) {
        float vS = accS[h], vD = accD[h];
        #pragma unroll
        for (int o = 16; o > 0; o >>= 1) {
            vS += __shfl_down_sync(0xffffffffu, vS, o);
            vD += __shfl_down_sync(0xffffffffu, vD, o);
        }
        if (lane == 0) { aS[warp * 4 + h] = vS; aD[warp * 4 + h] = vD; }
    }
}

// pass 1: e = leaky_relu(a_s[src] + a_d[dst]); store e; segment max into m[dst]
__global__ void k_edge1(const int* __restrict__ src, const int* __restrict__ dst,
                        const float* __restrict__ aS, const float* __restrict__ aD,
                        float* __restrict__ m, float* __restrict__ ebuf) {
    int idx = blockIdx.x * blockDim.x + threadIdx.x;
    if (idx >= ETOT) return;
    int s, d;
    if (idx < NEDGE) { s = src[idx]; d = dst[idx]; }
    else             { s = d = idx - NEDGE; }
    float4 vs = *(const float4*)(aS + s * 4);
    float4 vd = *(const float4*)(aD + d * 4);
    float e0 = vs.x + vd.x; e0 = e0 > 0.0f ? e0 : 0.2f * e0;
    float e1 = vs.y + vd.y; e1 = e1 > 0.0f ? e1 : 0.2f * e1;
    float e2 = vs.z + vd.z; e2 = e2 > 0.0f ? e2 : 0.2f * e2;
    float e3 = vs.w + vd.w; e3 = e3 > 0.0f ? e3 : 0.2f * e3;
    *(float4*)(ebuf + idx * 4) = make_float4(e0, e1, e2, e3);
    atomicMaxF(&m[d * 4 + 0], e0);
    atomicMaxF(&m[d * 4 + 1], e1);
    atomicMaxF(&m[d * 4 + 2], e2);
    atomicMaxF(&m[d * 4 + 3], e3);
}

// pass 2: ex = exp(e - m[dst]); store ex over e; segment sum into s[dst]
__global__ void k_edge2(const int* __restrict__ src, const int* __restrict__ dst,
                        const float* __restrict__ m, float* __restrict__ ebuf,
                        float* __restrict__ sbuf) {
    int idx = blockIdx.x * blockDim.x + threadIdx.x;
    if (idx >= ETOT) return;
    int d;
    if (idx < NEDGE) d = dst[idx];
    else             d = idx - NEDGE;
    float4 e = *(const float4*)(ebuf + idx * 4);
    float4 mv = *(const float4*)(m + d * 4);
    float x0 = expf(e.x - mv.x);
    float x1 = expf(e.y - mv.y);
    float x2 = expf(e.z - mv.z);
    float x3 = expf(e.w - mv.w);
    *(float4*)(ebuf + idx * 4) = make_float4(x0, x1, x2, x3);
    atomicAdd(&sbuf[d * 4 + 0], x0);
    atomicAdd(&sbuf[d * 4 + 1], x1);
    atomicAdd(&sbuf[d * 4 + 2], x2);
    atomicAdd(&sbuf[d * 4 + 3], x3);
}

// pass 3: out[dst] += h[src] * alpha.  One warp per edge, lane covers 8 floats.
__global__ void k_edge3(const int* __restrict__ src, const int* __restrict__ dst,
                        const float* __restrict__ H, const float* __restrict__ ebuf,
                        const float* __restrict__ sbuf, float* __restrict__ out) {
    int gw = (blockIdx.x * blockDim.x + threadIdx.x) >> 5;
    int lane = threadIdx.x & 31;
    if (gw >= ETOT) return;
    int s, d;
    if (gw < NEDGE) { s = src[gw]; d = dst[gw]; }
    else            { s = d = gw - NEDGE; }
    int head = lane >> 3;
    float alpha = ebuf[gw * 4 + head] / (sbuf[d * 4 + head] + 1e-16f);
    int base = lane * 8;
    const float4* hp = (const float4*)(H + s * DMODEL + base);
    float4 h0 = hp[0], h1 = hp[1];
    float* op = out + d * DMODEL + base;
    atomicAdd(op + 0, h0.x * alpha);
    atomicAdd(op + 1, h0.y * alpha);
    atomicAdd(op + 2, h0.z * alpha);
    atomicAdd(op + 3, h0.w * alpha);
    atomicAdd(op + 4, h1.x * alpha);
    atomicAdd(op + 5, h1.y * alpha);
    atomicAdd(op + 6, h1.z * alpha);
    atomicAdd(op + 7, h1.w * alpha);
}

// out = relu(out + bias)
__global__ void k_bias_relu(float* __restrict__ X, const float* __restrict__ bias, int N) {
    int idx = blockIdx.x * blockDim.x + threadIdx.x;
    if (idx >= N * DMODEL) return;
    float v = X[idx] + bias[idx & 255];
    X[idx] = v > 0.0f ? v : 0.0f;
}

// final: y = relu(x @ Wg + bg); out = y @ Wf + bf.  One block (64 thr) per node.
__global__ void k_final(const float* __restrict__ X, const float* __restrict__ Wg,
                        const float* __restrict__ bg, const float* __restrict__ Wf,
                        const float* __restrict__ bf, float* __restrict__ out) {
    __shared__ float y[FEAT];
    int node = blockIdx.x;
    int t = threadIdx.x;   // 0..63
    const float* xr = X + node * DMODEL;
    float acc = bg[t];
    #pragma unroll 4
    for (int k = 0; k < DMODEL; k++) acc += xr[k] * Wg[k * FEAT + t];
    acc = acc > 0.0f ? acc : 0.0f;
    y[t] = acc;
    __syncthreads();
    if (t < 5) {
        float o = bf[t];
        #pragma unroll
        for (int k = 0; k < FEAT; k++) o += y[k] * Wf[k * 5 + t];
        out[node * 5 + t] = o;
    }
}

// ---------------- host orchestration ----------------------------------------
extern "C" void kernel_launch(void* const* d_in, const int* in_sizes, int n_in,
                              void* d_out, int out_size) {
    const float* z     = (const float*)d_in[0];
    const int*   ei    = (const int*)d_in[1];
    const int*   batch = (const int*)d_in[2];
    // num_graphs may or may not be materialized as an input; detect by size
    int base = (in_sizes[3] == 1) ? 4 : 3;
    const float* W0  = (const float*)d_in[base + 0];
    const float* b0  = (const float*)d_in[base + 1];
    const float* W1  = (const float*)d_in[base + 2];
    const float* as1 = (const float*)d_in[base + 3];
    const float* ad1 = (const float*)d_in[base + 4];
    const float* bb1 = (const float*)d_in[base + 5];
    const float* W2  = (const float*)d_in[base + 6];
    const float* as2 = (const float*)d_in[base + 7];
    const float* ad2 = (const float*)d_in[base + 8];
    const float* bb2 = (const float*)d_in[base + 9];
    const float* W3  = (const float*)d_in[base + 10];
    const float* as3 = (const float*)d_in[base + 11];
    const float* ad3 = (const float*)d_in[base + 12];
    const float* bb3 = (const float*)d_in[base + 13];
    const float* Wg  = (const float*)d_in[base + 14];
    const float* bg  = (const float*)d_in[base + 15];
    const float* Wf  = (const float*)d_in[base + 16];
    const float* bf  = (const float*)d_in[base + 17];

    const int N = NNODE;
    const int* srcArr = ei;
    const int* dstArr = ei + NEDGE;

    float *bufA, *bufB, *aS, *aD, *mB, *sB, *eB, *x0B;
    int* startsB;
    cudaGetSymbolAddress((void**)&bufA, g_bufA);
    cudaGetSymbolAddress((void**)&bufB, g_bufB);
    cudaGetSymbolAddress((void**)&aS, g_as);
    cudaGetSymbolAddress((void**)&aD, g_ad);
    cudaGetSymbolAddress((void**)&mB, g_m);
    cudaGetSymbolAddress((void**)&sB, g_s);
    cudaGetSymbolAddress((void**)&eB, g_e);
    cudaGetSymbolAddress((void**)&x0B, g_x0);
    cudaGetSymbolAddress((void**)&startsB, g_starts);

    const int nElem = N * DMODEL;
    dim3 gemmGrid((N + BM - 1) / BM, DMODEL / BN);
    int edgeBlocks  = (ETOT + 255) / 256;
    int edge3Blocks = (ETOT + 7) / 8;       // 8 warps / block
    int attnBlocks  = (N + 7) / 8;

    // ---- prologue: x0, order, input features ----
    k_x0<<<NGRAPH, FEAT>>>(z, W0, b0, x0B);
    k_starts<<<(N + 255) / 256, 256>>>(batch, startsB, N);
    k_build<<<(nElem + 255) / 256, 256>>>(x0B, batch, startsB, bufA, N);

    // ---- 3 GAT layers ----
    const float* Ws[3]  = {W1, W2, W3};
    const float* ass[3] = {as1, as2, as3};
    const float* ads[3] = {ad1, ad2, ad3};
    const float* bbs[3] = {bb1, bb2, bb3};
    const int    kins[3] = {IN1, DMODEL, DMODEL};
    for (int l = 0; l < 3; l++) {
        k_gemm<<<gemmGrid, 256>>>(bufA, Ws[l], bufB, N, kins[l]);
        k_init<<<(nElem + 255) / 256, 256>>>(bufA, mB, sB, N);
        k_attn<<<attnBlocks, 256>>>(bufB, ass[l], ads[l], aS, aD, N);
        k_edge1<<<edgeBlocks, 256>>>(srcArr, dstArr, aS, aD, mB, eB);
        k_edge2<<<edgeBlocks, 256>>>(srcArr, dstArr, mB, eB, sB);
        k_edge3<<<edge3Blocks, 256>>>(srcArr, dstArr, bufB, eB, sB, bufA);
        k_bias_relu<<<(nElem + 255) / 256, 256>>>(bufA, bbs[l], N);
    }

    // ---- epilogue: dec_geo + fc_geo ----
    k_final<<<N, FEAT>>>(bufA, Wg, bg, Wf, bf, (float*)d_out);
}

// round 2
// speedup vs baseline: 3.7441x; 3.7441x over previous
#include <cuda_runtime.h>
#include <math.h>

// ---------------- problem constants -----------------------------------------
#define NNODE 19200
#define NEDGE 230400
#define NGRAPH 128
#define LATENT 256
#define FEAT 64
#define HEADS 4
#define POS 180
#define DMODEL 256       // HEADS * FEAT
#define ETOT (NEDGE + NNODE)

// ---------------- static device scratch --------------------------------------
__device__ __align__(16) float g_bufA[NNODE * DMODEL];   // layer input / aggregation out
__device__ __align__(16) float g_bufB[NNODE * DMODEL];   // h = x @ W
__device__ __align__(16) float g_as[NNODE * HEADS];
__device__ __align__(16) float g_ad[NNODE * HEADS];
__device__ __align__(16) float g_pg[NGRAPH * DMODEL];
__device__ __align__(16) float g_x0[NGRAPH * FEAT];
__device__ int g_starts[NGRAPH];
__device__ int g_deg[NNODE];
__device__ int g_rowptr[NNODE + 1];
__device__ int g_cursor[NNODE];
__device__ int g_csrc[ETOT];

// ---------------- prologue kernels -------------------------------------------

// x0 = z @ W0 + b0   [G,64]
__global__ void k_x0(const float* __restrict__ z, const float* __restrict__ W0,
                     const float* __restrict__ b0, float* __restrict__ x0) {
    int g = blockIdx.x, c = threadIdx.x;
    float acc = b0[c];
    const float* zr = z + g * LATENT;
    #pragma unroll 4
    for (int k = 0; k < LATENT; k++) acc += zr[k] * W0[k * FEAT + c];
    x0[g * FEAT + c] = acc;
}

__global__ void k_starts(const int* __restrict__ batch, int* __restrict__ starts, int N) {
    int i = blockIdx.x * blockDim.x + threadIdx.x;
    if (i >= N) return;
    int b = batch[i];
    if (i == 0 || batch[i - 1] != b) starts[b] = i;
}

// pg[g][c] = sum_{k<64} relu(x0[g,k]) * W1[k,c]
__global__ void k_pg(const float* __restrict__ x0, const float* __restrict__ W1,
                     float* __restrict__ pg) {
    __shared__ float xs[FEAT];
    int g = blockIdx.x, c = threadIdx.x;      // 256 threads
    if (c < FEAT) { float v = x0[g * FEAT + c]; xs[c] = v > 0.0f ? v : 0.0f; }
    __syncthreads();
    float acc = 0.0f;
    #pragma unroll
    for (int k = 0; k < FEAT; k++) acc += xs[k] * W1[k * DMODEL + c];
    pg[g * DMODEL + c] = acc;
}

// h1[node][c] = pg[batch[node]][c] + W1[64 + order][c]   (one-hot shortcut)
__global__ void k_h1(const float* __restrict__ pg, const float* __restrict__ W1,
                     const int* __restrict__ batch, const int* __restrict__ starts,
                     float* __restrict__ H) {
    int node = blockIdx.x;
    int c = threadIdx.x;                      // 256
    int g = batch[node];
    int order = node - starts[g];
    H[node * DMODEL + c] = pg[g * DMODEL + c] + W1[(FEAT + order) * DMODEL + c];
}

// ---------------- CSR build ---------------------------------------------------
__global__ void k_deg_init(int* __restrict__ deg, int N) {
    int i = blockIdx.x * blockDim.x + threadIdx.x;
    if (i < N) deg[i] = 1;                    // self loop slot
}
__global__ void k_hist(const int* __restrict__ dst, int* __restrict__ deg) {
    int e = blockIdx.x * blockDim.x + threadIdx.x;
    if (e < NEDGE) atomicAdd(&deg[dst[e]], 1);
}
// single-block exclusive scan -> rowptr
__global__ void k_scan(const int* __restrict__ deg, int* __restrict__ rowptr) {
    __shared__ int part[1024];
    int t = threadIdx.x;
    const int C = (NNODE + 1023) / 1024;      // 19
    int start = t * C, end = min(start + C, NNODE);
    int sum = 0;
    for (int i = start; i < end; i++) sum += deg[i];
    part[t] = sum;
    __syncthreads();
    for (int off = 1; off < 1024; off <<= 1) {
        int v = (t >= off) ? part[t - off] : 0;
        __syncthreads();
        part[t] += v;
        __syncthreads();
    }
    int run = (t > 0) ? part[t - 1] : 0;
    for (int i = start; i < end; i++) { rowptr[i] = run; run += deg[i]; }
    if (t == 1023) rowptr[NNODE] = run;
}
__global__ void k_fillself(const int* __restrict__ rowptr, int* __restrict__ cursor,
                           int* __restrict__ csrc, int N) {
    int i = blockIdx.x * blockDim.x + threadIdx.x;
    if (i >= N) return;
    int r = rowptr[i];
    csrc[r] = i;                              // self loop first
    cursor[i] = r + 1;
}
__global__ void k_scatter(const int* __restrict__ src, const int* __restrict__ dst,
                          int* __restrict__ cursor, int* __restrict__ csrc) {
    int e = blockIdx.x * blockDim.x + threadIdx.x;
    if (e >= NEDGE) return;
    int p = atomicAdd(&cursor[dst[e]], 1);
    csrc[p] = src[e];
}

// ---------------- GEMM: C[19200,256] = X[19200,256] @ W[256,256] --------------
#define GBM 128
#define GBN 128
#define GBK 16
__global__ void __launch_bounds__(256, 2)
k_gemm256(const float* __restrict__ X, const float* __restrict__ W,
          float* __restrict__ C) {
    __shared__ float As[GBK][GBM];
    __shared__ float Bs[GBK][GBN];
    int tid = threadIdx.x;
    int tx = tid & 15, ty = tid >> 4;
    int r0 = blockIdx.x * GBM, c0 = blockIdx.y * GBN;
    float acc[8][8] = {};
    int arow = tid >> 1;
    int akoff = (tid & 1) * 8;
    int bk = tid >> 5;                        // 0..7
    int bcol = (tid & 31) * 4;
    for (int k0 = 0; k0 < DMODEL; k0 += GBK) {
        const float* ap = X + (r0 + arow) * DMODEL + k0 + akoff;
        float4 av0 = *(const float4*)(ap);
        float4 av1 = *(const float4*)(ap + 4);
        As[akoff + 0][arow] = av0.x;
        As[akoff + 1][arow] = av0.y;
        As[akoff + 2][arow] = av0.z;
        As[akoff + 3][arow] = av0.w;
        As[akoff + 4][arow] = av1.x;
        As[akoff + 5][arow] = av1.y;
        As[akoff + 6][arow] = av1.z;
        As[akoff + 7][arow] = av1.w;
        *(float4*)&Bs[bk][bcol]     = *(const float4*)(W + (k0 + bk) * DMODEL + c0 + bcol);
        *(float4*)&Bs[bk + 8][bcol] = *(const float4*)(W + (k0 + bk + 8) * DMODEL + c0 + bcol);
        __syncthreads();
        #pragma unroll
        for (int k = 0; k < GBK; k++) {
            float a[8], b[8];
            *(float4*)&a[0] = *(const float4*)&As[k][ty * 8];
            *(float4*)&a[4] = *(const float4*)&As[k][ty * 8 + 4];
            *(float4*)&b[0] = *(const float4*)&Bs[k][tx * 8];
            *(float4*)&b[4] = *(const float4*)&Bs[k][tx * 8 + 4];
            #pragma unroll
            for (int i = 0; i < 8; i++)
                #pragma unroll
                for (int j = 0; j < 8; j++)
                    acc[i][j] += a[i] * b[j];
        }
        __syncthreads();
    }
    #pragma unroll
    for (int i = 0; i < 8; i++) {
        float* cp = C + (r0 + ty * 8 + i) * DMODEL + c0 + tx * 8;
        *(float4*)cp       = make_float4(acc[i][0], acc[i][1], acc[i][2], acc[i][3]);
        *(float4*)(cp + 4) = make_float4(acc[i][4], acc[i][5], acc[i][6], acc[i][7]);
    }
}

// ---------------- attention logits --------------------------------------------
__global__ void k_attn(const float* __restrict__ H, const float* __restrict__ attS,
                       const float* __restrict__ attD, float* __restrict__ aS,
                       float* __restrict__ aD, int N) {
    __shared__ float sS[DMODEL], sD[DMODEL];
    int tid = threadIdx.x;
    if (tid < DMODEL) { sS[tid] = attS[tid]; sD[tid] = attD[tid]; }
    __syncthreads();
    int warp = (blockIdx.x * blockDim.x + tid) >> 5;
    int lane = tid & 31;
    if (warp >= N) return;
    const float* hr = H + warp * DMODEL;
    float accS[4] = {0, 0, 0, 0}, accD[4] = {0, 0, 0, 0};
    #pragma unroll
    for (int c = 0; c < 8; c++) {
        int p = c * 32 + lane;
        float hv = hr[p];
        accS[c >> 1] += hv * sS[p];
        accD[c >> 1] += hv * sD[p];
    }
    #pragma unroll
    for (int h = 0; h < 4; h++) {
        float vS = accS[h], vD = accD[h];
        #pragma unroll
        for (int o = 16; o > 0; o >>= 1) {
            vS += __shfl_down_sync(0xffffffffu, vS, o);
            vD += __shfl_down_sync(0xffffffffu, vD, o);
        }
        if (lane == 0) { aS[warp * 4 + h] = vS; aD[warp * 4 + h] = vD; }
    }
}

// ---------------- fused segment softmax + weighted aggregate ------------------
// one warp per dst node; no atomics; epilogue = relu(acc + bias)
__device__ __forceinline__ float lrelu(float v) { return v > 0.0f ? v : 0.2f * v; }

__global__ void k_aggregate(const int* __restrict__ rowptr, const int* __restrict__ csrc,
                            const float* __restrict__ H, const float* __restrict__ aS,
                            const float* __restrict__ aD, const float* __restrict__ bias,
                            float* __restrict__ out) {
    int warp = (blockIdx.x * blockDim.x + threadIdx.x) >> 5;
    int lane = threadIdx.x & 31;
    if (warp >= NNODE) return;
    int rs = rowptr[warp], re = rowptr[warp + 1];
    float4 ad = *(const float4*)(aD + warp * 4);

    // pass 1: segment max per head
    float m0 = -1e30f, m1 = -1e30f, m2 = -1e30f, m3 = -1e30f;
    for (int e = rs + lane; e < re; e += 32) {
        int s = csrc[e];
        float4 as = *(const float4*)(aS + s * 4);
        m0 = fmaxf(m0, lrelu(as.x + ad.x));
        m1 = fmaxf(m1, lrelu(as.y + ad.y));
        m2 = fmaxf(m2, lrelu(as.z + ad.z));
        m3 = fmaxf(m3, lrelu(as.w + ad.w));
    }
    #pragma unroll
    for (int o = 16; o > 0; o >>= 1) {
        m0 = fmaxf(m0, __shfl_xor_sync(0xffffffffu, m0, o));
        m1 = fmaxf(m1, __shfl_xor_sync(0xffffffffu, m1, o));
        m2 = fmaxf(m2, __shfl_xor_sync(0xffffffffu, m2, o));
        m3 = fmaxf(m3, __shfl_xor_sync(0xffffffffu, m3, o));
    }
    // pass 1b: segment sum of exp
    float s0 = 0, s1 = 0, s2 = 0, s3 = 0;
    for (int e = rs + lane; e < re; e += 32) {
        int s = csrc[e];
        float4 as = *(const float4*)(aS + s * 4);
        s0 += expf(lrelu(as.x + ad.x) - m0);
        s1 += expf(lrelu(as.y + ad.y) - m1);
        s2 += expf(lrelu(as.z + ad.z) - m2);
        s3 += expf(lrelu(as.w + ad.w) - m3);
    }
    #pragma unroll
    for (int o = 16; o > 0; o >>= 1) {
        s0 += __shfl_xor_sync(0xffffffffu, s0, o);
        s1 += __shfl_xor_sync(0xffffffffu, s1, o);
        s2 += __shfl_xor_sync(0xffffffffu, s2, o);
        s3 += __shfl_xor_sync(0xffffffffu, s3, o);
    }
    int head = lane >> 3;
    float mh  = head == 0 ? m0 : head == 1 ? m1 : head == 2 ? m2 : m3;
    float sh  = head == 0 ? s0 : head == 1 ? s1 : head == 2 ? s2 : s3;
    float adh = head == 0 ? ad.x : head == 1 ? ad.y : head == 2 ? ad.z : ad.w;
    float inv = 1.0f / (sh + 1e-16f);

    // pass 2: weighted feature aggregation (lane owns 8 contiguous features)
    float acc[8] = {};
    int sNext = csrc[rs];
    for (int e = rs; e < re; e++) {
        int s = sNext;
        if (e + 1 < re) sNext = csrc[e + 1];
        float ash = __ldg(aS + s * 4 + head);
        float alpha = expf(lrelu(ash + adh) - mh) * inv;
        const float4* hp = (const float4*)(H + s * DMODEL + lane * 8);
        float4 h0 = hp[0], h1 = hp[1];
        acc[0] += alpha * h0.x; acc[1] += alpha * h0.y;
        acc[2] += alpha * h0.z; acc[3] += alpha * h0.w;
        acc[4] += alpha * h1.x; acc[5] += alpha * h1.y;
        acc[6] += alpha * h1.z; acc[7] += alpha * h1.w;
    }
    const float4* bp = (const float4*)(bias + lane * 8);
    float4 b0 = bp[0], b1 = bp[1];
    float r[8];
    r[0] = acc[0] + b0.x; r[1] = acc[1] + b0.y; r[2] = acc[2] + b0.z; r[3] = acc[3] + b0.w;
    r[4] = acc[4] + b1.x; r[5] = acc[5] + b1.y; r[6] = acc[6] + b1.z; r[7] = acc[7] + b1.w;
    #pragma unroll
    for (int i = 0; i < 8; i++) r[i] = r[i] > 0.0f ? r[i] : 0.0f;
    float* op = out + warp * DMODEL + lane * 8;
    *(float4*)op       = make_float4(r[0], r[1], r[2], r[3]);
    *(float4*)(op + 4) = make_float4(r[4], r[5], r[6], r[7]);
}

// ---------------- epilogue -----------------------------------------------------
__global__ void k_final(const float* __restrict__ X, const float* __restrict__ Wg,
                        const float* __restrict__ bg, const float* __restrict__ Wf,
                        const float* __restrict__ bf, float* __restrict__ out) {
    __shared__ float y[FEAT];
    int node = blockIdx.x;
    int t = threadIdx.x;                      // 0..63
    const float* xr = X + node * DMODEL;
    float acc = bg[t];
    #pragma unroll 4
    for (int k = 0; k < DMODEL; k++) acc += xr[k] * Wg[k * FEAT + t];
    acc = acc > 0.0f ? acc : 0.0f;
    y[t] = acc;
    __syncthreads();
    if (t < 5) {
        float o = bf[t];
        #pragma unroll
        for (int k = 0; k < FEAT; k++) o += y[k] * Wf[k * 5 + t];
        out[node * 5 + t] = o;
    }
}

// ---------------- host orchestration ------------------------------------------
extern "C" void kernel_launch(void* const* d_in, const int* in_sizes, int n_in,
                              void* d_out, int out_size) {
    const float* z     = (const float*)d_in[0];
    const int*   ei    = (const int*)d_in[1];
    const int*   batch = (const int*)d_in[2];
    int base = (in_sizes[3] == 1) ? 4 : 3;
    const float* W0  = (const float*)d_in[base + 0];
    const float* b0  = (const float*)d_in[base + 1];
    const float* W1  = (const float*)d_in[base + 2];
    const float* as1 = (const float*)d_in[base + 3];
    const float* ad1 = (const float*)d_in[base + 4];
    const float* bb1 = (const float*)d_in[base + 5];
    const float* W2  = (const float*)d_in[base + 6];
    const float* as2 = (const float*)d_in[base + 7];
    const float* ad2 = (const float*)d_in[base + 8];
    const float* bb2 = (const float*)d_in[base + 9];
    const float* W3  = (const float*)d_in[base + 10];
    const float* as3 = (const float*)d_in[base + 11];
    const float* ad3 = (const float*)d_in[base + 12];
    const float* bb3 = (const float*)d_in[base + 13];
    const float* Wg  = (const float*)d_in[base + 14];
    const float* bg  = (const float*)d_in[base + 15];
    const float* Wf  = (const float*)d_in[base + 16];
    const float* bf  = (const float*)d_in[base + 17];

    const int N = NNODE;
    const int* srcArr = ei;
    const int* dstArr = ei + NEDGE;

    float *bufA, *bufB, *aS, *aD, *x0B, *pgB;
    int *startsB, *degB, *rowptrB, *cursorB, *csrcB;
    cudaGetSymbolAddress((void**)&bufA, g_bufA);
    cudaGetSymbolAddress((void**)&bufB, g_bufB);
    cudaGetSymbolAddress((void**)&aS, g_as);
    cudaGetSymbolAddress((void**)&aD, g_ad);
    cudaGetSymbolAddress((void**)&x0B, g_x0);
    cudaGetSymbolAddress((void**)&pgB, g_pg);
    cudaGetSymbolAddress((void**)&startsB, g_starts);
    cudaGetSymbolAddress((void**)&degB, g_deg);
    cudaGetSymbolAddress((void**)&rowptrB, g_rowptr);
    cudaGetSymbolAddress((void**)&cursorB, g_cursor);
    cudaGetSymbolAddress((void**)&csrcB, g_csrc);

    // ---- CSR build (runs every replay; small) ----
    k_deg_init<<<(N + 255) / 256, 256>>>(degB, N);
    k_hist<<<(NEDGE + 255) / 256, 256>>>(dstArr, degB);
    k_scan<<<1, 1024>>>(degB, rowptrB);
    k_fillself<<<(N + 255) / 256, 256>>>(rowptrB, cursorB, csrcB, N);
    k_scatter<<<(NEDGE + 255) / 256, 256>>>(srcArr, dstArr, cursorB, csrcB);

    // ---- prologue ----
    k_x0<<<NGRAPH, FEAT>>>(z, W0, b0, x0B);
    k_starts<<<(N + 255) / 256, 256>>>(batch, startsB, N);
    k_pg<<<NGRAPH, DMODEL>>>(x0B, W1, pgB);
    k_h1<<<N, DMODEL>>>(pgB, W1, batch, startsB, bufB);   // h for layer 1

    dim3 gemmGrid(N / GBM, DMODEL / GBN);
    int warpBlocks = (N + 7) / 8;                         // 8 warps / block

    // ---- layer 1 (h already in bufB) ----
    k_attn<<<warpBlocks, 256>>>(bufB, as1, ad1, aS, aD, N);
    k_aggregate<<<warpBlocks, 256>>>(rowptrB, csrcB, bufB, aS, aD, bb1, bufA);

    // ---- layers 2,3 ----
    const float* Ws[2]  = {W2, W3};
    const float* ass[2] = {as2, as3};
    const float* ads[2] = {ad2, ad3};
    const float* bbs[2] = {bb2, bb3};
    for (int l = 0; l < 2; l++) {
        k_gemm256<<<gemmGrid, 256>>>(bufA, Ws[l], bufB);
        k_attn<<<warpBlocks, 256>>>(bufB, ass[l], ads[l], aS, aD, N);
        k_aggregate<<<warpBlocks, 256>>>(rowptrB, csrcB, bufB, aS, aD, bbs[l], bufA);
    }

    // ---- epilogue ----
    k_final<<<N, FEAT>>>(bufA, Wg, bg, Wf, bf, (float*)d_out);
}

// round 3
// speedup vs baseline: 3.9348x; 1.0509x over previous
#include <cuda_runtime.h>
#include <math.h>

// ---------------- problem constants -----------------------------------------
#define NNODE 19200
#define NEDGE 230400
#define NGRAPH 128
#define LATENT 256
#define FEAT 64
#define HEADS 4
#define POS 180
#define DMODEL 256       // HEADS * FEAT
#define ETOT (NEDGE + NNODE)

// ---------------- static device scratch --------------------------------------
__device__ __align__(16) float g_bufA[NNODE * DMODEL];   // layer input / aggregation out
__device__ __align__(16) float g_bufB[NNODE * DMODEL];   // h = x @ W
__device__ __align__(16) float g_as[NNODE * HEADS];
__device__ __align__(16) float g_ad[NNODE * HEADS];
__device__ __align__(16) float g_ex[ETOT * HEADS];       // exp(e - m) per CSR slot
__device__ __align__(16) float g_pg[NGRAPH * DMODEL];
__device__ __align__(16) float g_x0[NGRAPH * FEAT];
__device__ int g_starts[NGRAPH];
__device__ int g_deg[NNODE];
__device__ int g_rowptr[NNODE + 1];
__device__ int g_cursor[NNODE];
__device__ int g_csrc[ETOT];

// ---------------- prologue kernels -------------------------------------------
__global__ void k_x0(const float* __restrict__ z, const float* __restrict__ W0,
                     const float* __restrict__ b0, float* __restrict__ x0) {
    int g = blockIdx.x, c = threadIdx.x;
    float acc = b0[c];
    const float* zr = z + g * LATENT;
    #pragma unroll 4
    for (int k = 0; k < LATENT; k++) acc += zr[k] * W0[k * FEAT + c];
    x0[g * FEAT + c] = acc;
}

__global__ void k_starts(const int* __restrict__ batch, int* __restrict__ starts, int N) {
    int i = blockIdx.x * blockDim.x + threadIdx.x;
    if (i >= N) return;
    int b = batch[i];
    if (i == 0 || batch[i - 1] != b) starts[b] = i;
}

__global__ void k_pg(const float* __restrict__ x0, const float* __restrict__ W1,
                     float* __restrict__ pg) {
    __shared__ float xs[FEAT];
    int g = blockIdx.x, c = threadIdx.x;      // 256 threads
    if (c < FEAT) { float v = x0[g * FEAT + c]; xs[c] = v > 0.0f ? v : 0.0f; }
    __syncthreads();
    float acc = 0.0f;
    #pragma unroll
    for (int k = 0; k < FEAT; k++) acc += xs[k] * W1[k * DMODEL + c];
    pg[g * DMODEL + c] = acc;
}

__global__ void k_h1(const float* __restrict__ pg, const float* __restrict__ W1,
                     const int* __restrict__ batch, const int* __restrict__ starts,
                     float* __restrict__ H) {
    int node = blockIdx.x;
    int c = threadIdx.x;                      // 256
    int g = batch[node];
    int order = node - starts[g];
    H[node * DMODEL + c] = pg[g * DMODEL + c] + W1[(FEAT + order) * DMODEL + c];
}

// ---------------- CSR build ---------------------------------------------------
__global__ void k_deg_init(int* __restrict__ deg, int N) {
    int i = blockIdx.x * blockDim.x + threadIdx.x;
    if (i < N) deg[i] = 1;                    // self loop slot
}
__global__ void k_hist(const int* __restrict__ dst, int* __restrict__ deg) {
    int e = blockIdx.x * blockDim.x + threadIdx.x;
    if (e < NEDGE) atomicAdd(&deg[dst[e]], 1);
}
__global__ void k_scan(const int* __restrict__ deg, int* __restrict__ rowptr) {
    __shared__ int part[1024];
    int t = threadIdx.x;
    const int C = (NNODE + 1023) / 1024;
    int start = t * C, end = min(start + C, NNODE);
    int sum = 0;
    for (int i = start; i < end; i++) sum += deg[i];
    part[t] = sum;
    __syncthreads();
    for (int off = 1; off < 1024; off <<= 1) {
        int v = (t >= off) ? part[t - off] : 0;
        __syncthreads();
        part[t] += v;
        __syncthreads();
    }
    int run = (t > 0) ? part[t - 1] : 0;
    for (int i = start; i < end; i++) { rowptr[i] = run; run += deg[i]; }
    if (t == 1023) rowptr[NNODE] = run;
}
__global__ void k_fillself(const int* __restrict__ rowptr, int* __restrict__ cursor,
                           int* __restrict__ csrc, int N) {
    int i = blockIdx.x * blockDim.x + threadIdx.x;
    if (i >= N) return;
    int r = rowptr[i];
    csrc[r] = i;
    cursor[i] = r + 1;
}
__global__ void k_scatter(const int* __restrict__ src, const int* __restrict__ dst,
                          int* __restrict__ cursor, int* __restrict__ csrc) {
    int e = blockIdx.x * blockDim.x + threadIdx.x;
    if (e >= NEDGE) return;
    int p = atomicAdd(&cursor[dst[e]], 1);
    csrc[p] = src[e];
}

// ---------------- GEMM: C[19200,256] = X[19200,256] @ W[256,256] --------------
// 128x128x16 tile, register-staged double buffering.
#define GBM 128
#define GBN 128
#define GBK 16
__global__ void __launch_bounds__(256, 2)
k_gemm256(const float* __restrict__ X, const float* __restrict__ W,
          float* __restrict__ C) {
    __shared__ float As[GBK][GBM];
    __shared__ float Bs[GBK][GBN];
    int tid = threadIdx.x;
    int tx = tid & 15, ty = tid >> 4;
    int r0 = blockIdx.x * GBM, c0 = blockIdx.y * GBN;
    float acc[8][8] = {};
    int arow = tid >> 1;
    int akoff = (tid & 1) * 8;
    int bk = tid >> 5;
    int bcol = (tid & 31) * 4;

    const float* apBase = X + (r0 + arow) * DMODEL + akoff;
    const float* bpBase = W + bk * DMODEL + c0 + bcol;

    // preload tile 0
    float4 av0 = *(const float4*)(apBase);
    float4 av1 = *(const float4*)(apBase + 4);
    float4 bv0 = *(const float4*)(bpBase);
    float4 bv1 = *(const float4*)(bpBase + 8 * DMODEL);

    #pragma unroll 1
    for (int k0 = 0; k0 < DMODEL; k0 += GBK) {
        As[akoff + 0][arow] = av0.x; As[akoff + 1][arow] = av0.y;
        As[akoff + 2][arow] = av0.z; As[akoff + 3][arow] = av0.w;
        As[akoff + 4][arow] = av1.x; As[akoff + 5][arow] = av1.y;
        As[akoff + 6][arow] = av1.z; As[akoff + 7][arow] = av1.w;
        *(float4*)&Bs[bk][bcol]     = bv0;
        *(float4*)&Bs[bk + 8][bcol] = bv1;
        __syncthreads();

        if (k0 + GBK < DMODEL) {
            const float* ap = apBase + (k0 + GBK);
            const float* bp = bpBase + (k0 + GBK) * DMODEL;
            av0 = *(const float4*)(ap);
            av1 = *(const float4*)(ap + 4);
            bv0 = *(const float4*)(bp);
            bv1 = *(const float4*)(bp + 8 * DMODEL);
        }

        #pragma unroll
        for (int k = 0; k < GBK; k++) {
            float a[8], b[8];
            *(float4*)&a[0] = *(const float4*)&As[k][ty * 8];
            *(float4*)&a[4] = *(const float4*)&As[k][ty * 8 + 4];
            *(float4*)&b[0] = *(const float4*)&Bs[k][tx * 8];
            *(float4*)&b[4] = *(const float4*)&Bs[k][tx * 8 + 4];
            #pragma unroll
            for (int i = 0; i < 8; i++)
                #pragma unroll
                for (int j = 0; j < 8; j++)
                    acc[i][j] += a[i] * b[j];
        }
        __syncthreads();
    }
    #pragma unroll
    for (int i = 0; i < 8; i++) {
        float* cp = C + (r0 + ty * 8 + i) * DMODEL + c0 + tx * 8;
        *(float4*)cp       = make_float4(acc[i][0], acc[i][1], acc[i][2], acc[i][3]);
        *(float4*)(cp + 4) = make_float4(acc[i][4], acc[i][5], acc[i][6], acc[i][7]);
    }
}

// ---------------- attention logits --------------------------------------------
__global__ void k_attn(const float* __restrict__ H, const float* __restrict__ attS,
                       const float* __restrict__ attD, float* __restrict__ aS,
                       float* __restrict__ aD, int N) {
    __shared__ float sS[DMODEL], sD[DMODEL];
    int tid = threadIdx.x;
    if (tid < DMODEL) { sS[tid] = attS[tid]; sD[tid] = attD[tid]; }
    __syncthreads();
    int warp = (blockIdx.x * blockDim.x + tid) >> 5;
    int lane = tid & 31;
    if (warp >= N) return;
    const float* hr = H + warp * DMODEL;
    float accS[4] = {0, 0, 0, 0}, accD[4] = {0, 0, 0, 0};
    #pragma unroll
    for (int c = 0; c < 8; c++) {
        int p = c * 32 + lane;
        float hv = hr[p];
        accS[c >> 1] += hv * sS[p];
        accD[c >> 1] += hv * sD[p];
    }
    #pragma unroll
    for (int h = 0; h < 4; h++) {
        float vS = accS[h], vD = accD[h];
        #pragma unroll
        for (int o = 16; o > 0; o >>= 1) {
            vS += __shfl_down_sync(0xffffffffu, vS, o);
            vD += __shfl_down_sync(0xffffffffu, vD, o);
        }
        if (lane == 0) { aS[warp * 4 + h] = vS; aD[warp * 4 + h] = vD; }
    }
}

// ---------------- fused segment softmax + weighted aggregate ------------------
__device__ __forceinline__ float lrelu(float v) { return v > 0.0f ? v : 0.2f * v; }

__global__ void k_aggregate(const int* __restrict__ rowptr, const int* __restrict__ csrc,
                            const float* __restrict__ H, const float* __restrict__ aS,
                            const float* __restrict__ aD, const float* __restrict__ bias,
                            float* __restrict__ ex, float* __restrict__ out) {
    int warp = (blockIdx.x * blockDim.x + threadIdx.x) >> 5;
    int lane = threadIdx.x & 31;
    if (warp >= NNODE) return;
    int rs = rowptr[warp], re = rowptr[warp + 1];
    float4 ad = *(const float4*)(aD + warp * 4);

    // pass 1: segment max per head
    float m0 = -1e30f, m1 = -1e30f, m2 = -1e30f, m3 = -1e30f;
    for (int e = rs + lane; e < re; e += 32) {
        int s = csrc[e];
        float4 as = *(const float4*)(aS + s * 4);
        m0 = fmaxf(m0, lrelu(as.x + ad.x));
        m1 = fmaxf(m1, lrelu(as.y + ad.y));
        m2 = fmaxf(m2, lrelu(as.z + ad.z));
        m3 = fmaxf(m3, lrelu(as.w + ad.w));
    }
    #pragma unroll
    for (int o = 16; o > 0; o >>= 1) {
        m0 = fmaxf(m0, __shfl_xor_sync(0xffffffffu, m0, o));
        m1 = fmaxf(m1, __shfl_xor_sync(0xffffffffu, m1, o));
        m2 = fmaxf(m2, __shfl_xor_sync(0xffffffffu, m2, o));
        m3 = fmaxf(m3, __shfl_xor_sync(0xffffffffu, m3, o));
    }
    // pass 1b: exp, store per-edge, segment sum
    float s0 = 0, s1 = 0, s2 = 0, s3 = 0;
    for (int e = rs + lane; e < re; e += 32) {
        int s = csrc[e];
        float4 as = *(const float4*)(aS + s * 4);
        float x0 = expf(lrelu(as.x + ad.x) - m0);
        float x1 = expf(lrelu(as.y + ad.y) - m1);
        float x2 = expf(lrelu(as.z + ad.z) - m2);
        float x3 = expf(lrelu(as.w + ad.w) - m3);
        *(float4*)(ex + e * 4) = make_float4(x0, x1, x2, x3);
        s0 += x0; s1 += x1; s2 += x2; s3 += x3;
    }
    #pragma unroll
    for (int o = 16; o > 0; o >>= 1) {
        s0 += __shfl_xor_sync(0xffffffffu, s0, o);
        s1 += __shfl_xor_sync(0xffffffffu, s1, o);
        s2 += __shfl_xor_sync(0xffffffffu, s2, o);
        s3 += __shfl_xor_sync(0xffffffffu, s3, o);
    }
    int head = lane >> 3;
    float sh = head == 0 ? s0 : head == 1 ? s1 : head == 2 ? s2 : s3;
    float inv = 1.0f / (sh + 1e-16f);

    // pass 2: weighted feature aggregation (no expf)
    float acc[8] = {};
    int sNext = csrc[rs];
    for (int e = rs; e < re; e++) {
        int s = sNext;
        if (e + 1 < re) sNext = csrc[e + 1];
        float alpha = __ldg(ex + e * 4 + head) * inv;
        const float4* hp = (const float4*)(H + s * DMODEL + lane * 8);
        float4 h0 = hp[0], h1 = hp[1];
        acc[0] += alpha * h0.x; acc[1] += alpha * h0.y;
        acc[2] += alpha * h0.z; acc[3] += alpha * h0.w;
        acc[4] += alpha * h1.x; acc[5] += alpha * h1.y;
        acc[6] += alpha * h1.z; acc[7] += alpha * h1.w;
    }
    const float4* bp = (const float4*)(bias + lane * 8);
    float4 b0 = bp[0], b1 = bp[1];
    float r[8];
    r[0] = acc[0] + b0.x; r[1] = acc[1] + b0.y; r[2] = acc[2] + b0.z; r[3] = acc[3] + b0.w;
    r[4] = acc[4] + b1.x; r[5] = acc[5] + b1.y; r[6] = acc[6] + b1.z; r[7] = acc[7] + b1.w;
    #pragma unroll
    for (int i = 0; i < 8; i++) r[i] = r[i] > 0.0f ? r[i] : 0.0f;
    float* op = out + warp * DMODEL + lane * 8;
    *(float4*)op       = make_float4(r[0], r[1], r[2], r[3]);
    *(float4*)(op + 4) = make_float4(r[4], r[5], r[6], r[7]);
}

// ---------------- epilogue: y = relu(X@Wg+bg); out = y@Wf+bf -------------------
// 64 nodes per block, Wg staged through smem in 64-row chunks.
#define FB 64   // nodes per block
__global__ void __launch_bounds__(256)
k_final(const float* __restrict__ X, const float* __restrict__ Wg,
        const float* __restrict__ bg, const float* __restrict__ Wf,
        const float* __restrict__ bf, float* __restrict__ out) {
    __shared__ float sWg[64][FEAT];          // 16 KB (one 64-row K chunk)
    __shared__ float sy[FB][FEAT + 1];       // 16.25 KB, padded
    __shared__ float sWf[FEAT * 5];          // 1.25 KB

    int tid = threadIdx.x;
    int node0 = blockIdx.x * FB;
    int nodeL = tid >> 2;                    // 0..63
    int f0 = (tid & 3) * 16;                 // feature group base

    for (int i = tid; i < FEAT * 5; i += 256) sWf[i] = Wf[i];

    float acc[16];
    {
        float4 g0 = *(const float4*)(bg + f0);
        float4 g1 = *(const float4*)(bg + f0 + 4);
        float4 g2 = *(const float4*)(bg + f0 + 8);
        float4 g3 = *(const float4*)(bg + f0 + 12);
        acc[0] = g0.x; acc[1] = g0.y; acc[2] = g0.z; acc[3] = g0.w;
        acc[4] = g1.x; acc[5] = g1.y; acc[6] = g1.z; acc[7] = g1.w;
        acc[8] = g2.x; acc[9] = g2.y; acc[10] = g2.z; acc[11] = g2.w;
        acc[12] = g3.x; acc[13] = g3.y; acc[14] = g3.z; acc[15] = g3.w;
    }

    const float* xr = X + (node0 + nodeL) * DMODEL;
    #pragma unroll 1
    for (int kc = 0; kc < DMODEL; kc += 64) {
        // stage 64x64 chunk of Wg
        #pragma unroll
        for (int t = 0; t < 4; t++) {
            int idx = (tid + t * 256) * 4;   // float4 granularity
            *(float4*)&sWg[idx >> 6][idx & 63] = *(const float4*)(Wg + (kc << 6) + idx);
        }
        __syncthreads();
        #pragma unroll
        for (int k4 = 0; k4 < 16; k4++) {
            float4 xv = *(const float4*)(xr + kc + k4 * 4);
            #pragma unroll
            for (int kk = 0; kk < 4; kk++) {
                float x = kk == 0 ? xv.x : kk == 1 ? xv.y : kk == 2 ? xv.z : xv.w;
                const float* wrow = &sWg[k4 * 4 + kk][f0];
                float4 w0 = *(const float4*)(wrow);
                float4 w1 = *(const float4*)(wrow + 4);
                float4 w2 = *(const float4*)(wrow + 8);
                float4 w3 = *(const float4*)(wrow + 12);
                acc[0] += x * w0.x; acc[1] += x * w0.y; acc[2] += x * w0.z; acc[3] += x * w0.w;
                acc[4] += x * w1.x; acc[5] += x * w1.y; acc[6] += x * w1.z; acc[7] += x * w1.w;
                acc[8] += x * w2.x; acc[9] += x * w2.y; acc[10] += x * w2.z; acc[11] += x * w2.w;
                acc[12] += x * w3.x; acc[13] += x * w3.y; acc[14] += x * w3.z; acc[15] += x * w3.w;
            }
        }
        __syncthreads();
    }
    #pragma unroll
    for (int j = 0; j < 16; j++) {
        float v = acc[j];
        sy[nodeL][f0 + j] = v > 0.0f ? v : 0.0f;
    }
    __syncthreads();

    // stage 2: out[n,c] = bf[c] + sum_k y[n,k] * Wf[k,c]
    for (int idx = tid; idx < FB * 5; idx += 256) {
        int n = idx / 5, c = idx % 5;
        float o = bf[c];
        #pragma unroll
        for (int k = 0; k < FEAT; k++) o += sy[n][k] * sWf[k * 5 + c];
        out[(node0 + n) * 5 + c] = o;
    }
}

// ---------------- host orchestration ------------------------------------------
extern "C" void kernel_launch(void* const* d_in, const int* in_sizes, int n_in,
                              void* d_out, int out_size) {
    const float* z     = (const float*)d_in[0];
    const int*   ei    = (const int*)d_in[1];
    const int*   batch = (const int*)d_in[2];
    int base = (in_sizes[3] == 1) ? 4 : 3;
    const float* W0  = (const float*)d_in[base + 0];
    const float* b0  = (const float*)d_in[base + 1];
    const float* W1  = (const float*)d_in[base + 2];
    const float* as1 = (const float*)d_in[base + 3];
    const float* ad1 = (const float*)d_in[base + 4];
    const float* bb1 = (const float*)d_in[base + 5];
    const float* W2  = (const float*)d_in[base + 6];
    const float* as2 = (const float*)d_in[base + 7];
    const float* ad2 = (const float*)d_in[base + 8];
    const float* bb2 = (const float*)d_in[base + 9];
    const float* W3  = (const float*)d_in[base + 10];
    const float* as3 = (const float*)d_in[base + 11];
    const float* ad3 = (const float*)d_in[base + 12];
    const float* bb3 = (const float*)d_in[base + 13];
    const float* Wg  = (const float*)d_in[base + 14];
    const float* bg  = (const float*)d_in[base + 15];
    const float* Wf  = (const float*)d_in[base + 16];
    const float* bf  = (const float*)d_in[base + 17];

    const int N = NNODE;
    const int* srcArr = ei;
    const int* dstArr = ei + NEDGE;

    float *bufA, *bufB, *aS, *aD, *exB, *x0B, *pgB;
    int *startsB, *degB, *rowptrB, *cursorB, *csrcB;
    cudaGetSymbolAddress((void**)&bufA, g_bufA);
    cudaGetSymbolAddress((void**)&bufB, g_bufB);
    cudaGetSymbolAddress((void**)&aS, g_as);
    cudaGetSymbolAddress((void**)&aD, g_ad);
    cudaGetSymbolAddress((void**)&exB, g_ex);
    cudaGetSymbolAddress((void**)&x0B, g_x0);
    cudaGetSymbolAddress((void**)&pgB, g_pg);
    cudaGetSymbolAddress((void**)&startsB, g_starts);
    cudaGetSymbolAddress((void**)&degB, g_deg);
    cudaGetSymbolAddress((void**)&rowptrB, g_rowptr);
    cudaGetSymbolAddress((void**)&cursorB, g_cursor);
    cudaGetSymbolAddress((void**)&csrcB, g_csrc);

    // ---- CSR build ----
    k_deg_init<<<(N + 255) / 256, 256>>>(degB, N);
    k_hist<<<(NEDGE + 255) / 256, 256>>>(dstArr, degB);
    k_scan<<<1, 1024>>>(degB, rowptrB);
    k_fillself<<<(N + 255) / 256, 256>>>(rowptrB, cursorB, csrcB, N);
    k_scatter<<<(NEDGE + 255) / 256, 256>>>(srcArr, dstArr, cursorB, csrcB);

    // ---- prologue ----
    k_x0<<<NGRAPH, FEAT>>>(z, W0, b0, x0B);
    k_starts<<<(N + 255) / 256, 256>>>(batch, startsB, N);
    k_pg<<<NGRAPH, DMODEL>>>(x0B, W1, pgB);
    k_h1<<<N, DMODEL>>>(pgB, W1, batch, startsB, bufB);

    dim3 gemmGrid(N / GBM, DMODEL / GBN);
    int warpBlocks = (N + 7) / 8;

    // ---- layer 1 ----
    k_attn<<<warpBlocks, 256>>>(bufB, as1, ad1, aS, aD, N);
    k_aggregate<<<warpBlocks, 256>>>(rowptrB, csrcB, bufB, aS, aD, bb1, exB, bufA);

    // ---- layers 2,3 ----
    const float* Ws[2]  = {W2, W3};
    const float* ass[2] = {as2, as3};
    const float* ads[2] = {ad2, ad3};
    const float* bbs[2] = {bb2, bb3};
    for (int l = 0; l < 2; l++) {
        k_gemm256<<<gemmGrid, 256>>>(bufA, Ws[l], bufB);
        k_attn<<<warpBlocks, 256>>>(bufB, ass[l], ads[l], aS, aD, N);
        k_aggregate<<<warpBlocks, 256>>>(rowptrB, csrcB, bufB, aS, aD, bbs[l], exB, bufA);
    }

    // ---- epilogue ----
    k_final<<<N / FB, 256>>>(bufA, Wg, bg, Wf, bf, (float*)d_out);
}

// round 4
// speedup vs baseline: 4.0063x; 1.0182x over previous
#include <cuda_runtime.h>
#include <math.h>

// ---------------- problem constants -----------------------------------------
#define NNODE 19200
#define NEDGE 230400
#define NGRAPH 128
#define LATENT 256
#define FEAT 64
#define HEADS 4
#define POS 180
#define DMODEL 256       // HEADS * FEAT
#define ETOT (NEDGE + NNODE)

// ---------------- static device scratch --------------------------------------
__device__ __align__(16) float g_bufA[NNODE * DMODEL];   // layer input / aggregation out
__device__ __align__(16) float g_bufB[NNODE * DMODEL];   // h = x @ W
__device__ __align__(16) float g_as[NNODE * HEADS];
__device__ __align__(16) float g_ad[NNODE * HEADS];
__device__ __align__(16) float g_ex[ETOT * HEADS];       // exp(e - m) per CSR slot
__device__ __align__(16) float g_pg[NGRAPH * DMODEL];
__device__ int g_starts[NGRAPH];
__device__ int g_deg[NNODE];
__device__ int g_rowptr[NNODE + 1];
__device__ int g_cursor[NNODE];
__device__ int g_csrc[ETOT];

// ---------------- fused prologue: x0 = relu(z@W0+b0); pg = x0@W1[:64] ---------
__global__ void k_x0pg(const float* __restrict__ z, const float* __restrict__ W0,
                       const float* __restrict__ b0, const float* __restrict__ W1,
                       float* __restrict__ pg) {
    __shared__ float xs[FEAT];
    int g = blockIdx.x, t = threadIdx.x;      // 256 threads
    if (t < FEAT) {
        float acc = b0[t];
        const float* zr = z + g * LATENT;
        #pragma unroll 4
        for (int k = 0; k < LATENT; k++) acc += zr[k] * W0[k * FEAT + t];
        xs[t] = acc > 0.0f ? acc : 0.0f;
    }
    __syncthreads();
    float a = 0.0f;
    #pragma unroll
    for (int k = 0; k < FEAT; k++) a += xs[k] * W1[k * DMODEL + t];
    pg[g * DMODEL + t] = a;
}

// ---------------- fused: starts + deg init ------------------------------------
__global__ void k_prep(const int* __restrict__ batch, int* __restrict__ starts,
                       int* __restrict__ deg, int N) {
    int i = blockIdx.x * blockDim.x + threadIdx.x;
    if (i >= N) return;
    int b = batch[i];
    if (i == 0 || batch[i - 1] != b) starts[b] = i;
    deg[i] = 1;                               // self loop slot
}

__global__ void k_hist(const int* __restrict__ dst, int* __restrict__ deg) {
    int e = blockIdx.x * blockDim.x + threadIdx.x;
    if (e < NEDGE) atomicAdd(&deg[dst[e]], 1);
}

// fused: exclusive scan -> rowptr, plus self-loop fill + cursor init
__global__ void k_scan_fill(const int* __restrict__ deg, int* __restrict__ rowptr,
                            int* __restrict__ cursor, int* __restrict__ csrc) {
    __shared__ int part[1024];
    int t = threadIdx.x;
    const int C = (NNODE + 1023) / 1024;
    int start = t * C, end = min(start + C, NNODE);
    int sum = 0;
    for (int i = start; i < end; i++) sum += deg[i];
    part[t] = sum;
    __syncthreads();
    for (int off = 1; off < 1024; off <<= 1) {
        int v = (t >= off) ? part[t - off] : 0;
        __syncthreads();
        part[t] += v;
        __syncthreads();
    }
    int run = (t > 0) ? part[t - 1] : 0;
    for (int i = start; i < end; i++) {
        rowptr[i] = run;
        csrc[run] = i;                        // self loop first
        cursor[i] = run + 1;
        run += deg[i];
    }
    if (t == 1023) rowptr[NNODE] = run;
}

__global__ void k_scatter(const int* __restrict__ src, const int* __restrict__ dst,
                          int* __restrict__ cursor, int* __restrict__ csrc) {
    int e = blockIdx.x * blockDim.x + threadIdx.x;
    if (e >= NEDGE) return;
    int p = atomicAdd(&cursor[dst[e]], 1);
    csrc[p] = src[e];
}

// ---------------- fused: h1 build + attention logits ---------------------------
// one warp per node: H[node] = pg[batch] + W1[64+order]; aS/aD from same registers
__global__ void k_h1attn(const float* __restrict__ pg, const float* __restrict__ W1,
                         const int* __restrict__ batch, const int* __restrict__ starts,
                         const float* __restrict__ attS, const float* __restrict__ attD,
                         float* __restrict__ H, float* __restrict__ aS,
                         float* __restrict__ aD, int N) {
    __shared__ float sS[DMODEL], sD[DMODEL];
    int tid = threadIdx.x;
    if (tid < DMODEL) { sS[tid] = attS[tid]; sD[tid] = attD[tid]; }
    __syncthreads();
    int node = (blockIdx.x * blockDim.x + tid) >> 5;
    int lane = tid & 31;
    if (node >= N) return;
    int g = batch[node];
    int order = node - starts[g];
    int c0 = lane * 8;
    const float4* pgr = (const float4*)(pg + g * DMODEL + c0);
    const float4* w1r = (const float4*)(W1 + (FEAT + order) * DMODEL + c0);
    float4 p0 = pgr[0], p1 = pgr[1];
    float4 w0 = w1r[0], w1v = w1r[1];
    float h[8];
    h[0] = p0.x + w0.x; h[1] = p0.y + w0.y; h[2] = p0.z + w0.z; h[3] = p0.w + w0.w;
    h[4] = p1.x + w1v.x; h[5] = p1.y + w1v.y; h[6] = p1.z + w1v.z; h[7] = p1.w + w1v.w;
    float* hr = H + node * DMODEL + c0;
    *(float4*)hr       = make_float4(h[0], h[1], h[2], h[3]);
    *(float4*)(hr + 4) = make_float4(h[4], h[5], h[6], h[7]);
    float pS = 0.0f, pD = 0.0f;
    #pragma unroll
    for (int j = 0; j < 8; j++) { pS += h[j] * sS[c0 + j]; pD += h[j] * sD[c0 + j]; }
    pS += __shfl_xor_sync(0xffffffffu, pS, 1);
    pS += __shfl_xor_sync(0xffffffffu, pS, 2);
    pS += __shfl_xor_sync(0xffffffffu, pS, 4);
    pD += __shfl_xor_sync(0xffffffffu, pD, 1);
    pD += __shfl_xor_sync(0xffffffffu, pD, 2);
    pD += __shfl_xor_sync(0xffffffffu, pD, 4);
    if ((lane & 7) == 0) {
        int hd = lane >> 3;
        aS[node * 4 + hd] = pS;
        aD[node * 4 + hd] = pD;
    }
}

// ---------------- fused GEMM + attention logits --------------------------------
// C[19200,256] = X @ W; tile 128x256, 512 threads; aS/aD from accumulators.
#define GBM 128
#define GBK 16
__global__ void __launch_bounds__(512, 1)
k_gemm_attn(const float* __restrict__ X, const float* __restrict__ W,
            const float* __restrict__ attS, const float* __restrict__ attD,
            float* __restrict__ C, float* __restrict__ aS, float* __restrict__ aD) {
    __shared__ float As[GBK][GBM];
    __shared__ float Bs[GBK][DMODEL];
    __shared__ float sS[DMODEL], sD[DMODEL];
    int tid = threadIdx.x;
    if (tid < DMODEL) { sS[tid] = attS[tid]; sD[tid] = attD[tid]; }
    else if (tid < 2 * DMODEL) { /* covered above via second half */ }
    // (256..511 threads load nothing extra; 256 threads suffice)
    int tx = tid & 31, ty = tid >> 5;         // ty = warp id 0..15
    int r0 = blockIdx.x * GBM;
    float acc[8][8] = {};

    int arow = tid >> 2;                      // 0..127
    int akoff = (tid & 3) * 4;
    int bk = tid >> 6;                        // 0..7
    int bcol = (tid & 63) * 4;

    const float* apBase = X + (r0 + arow) * DMODEL + akoff;
    const float* bpBase = W + bk * DMODEL + bcol;

    float4 av = *(const float4*)(apBase);
    float4 bv0 = *(const float4*)(bpBase);
    float4 bv1 = *(const float4*)(bpBase + 8 * DMODEL);

    #pragma unroll 1
    for (int k0 = 0; k0 < DMODEL; k0 += GBK) {
        As[akoff + 0][arow] = av.x; As[akoff + 1][arow] = av.y;
        As[akoff + 2][arow] = av.z; As[akoff + 3][arow] = av.w;
        *(float4*)&Bs[bk][bcol]     = bv0;
        *(float4*)&Bs[bk + 8][bcol] = bv1;
        __syncthreads();
        if (k0 + GBK < DMODEL) {
            av  = *(const float4*)(apBase + k0 + GBK);
            const float* bp = bpBase + (k0 + GBK) * DMODEL;
            bv0 = *(const float4*)(bp);
            bv1 = *(const float4*)(bp + 8 * DMODEL);
        }
        #pragma unroll
        for (int k = 0; k < GBK; k++) {
            float a[8], b[8];
            *(float4*)&a[0] = *(const float4*)&As[k][ty * 8];
            *(float4*)&a[4] = *(const float4*)&As[k][ty * 8 + 4];
            *(float4*)&b[0] = *(const float4*)&Bs[k][tx * 8];
            *(float4*)&b[4] = *(const float4*)&Bs[k][tx * 8 + 4];
            #pragma unroll
            for (int i = 0; i < 8; i++)
                #pragma unroll
                for (int j = 0; j < 8; j++)
                    acc[i][j] += a[i] * b[j];
        }
        __syncthreads();
    }

    // store C + fused attention logits
    #pragma unroll
    for (int i = 0; i < 8; i++) {
        int row = r0 + ty * 8 + i;
        float* cp = C + row * DMODEL + tx * 8;
        *(float4*)cp       = make_float4(acc[i][0], acc[i][1], acc[i][2], acc[i][3]);
        *(float4*)(cp + 4) = make_float4(acc[i][4], acc[i][5], acc[i][6], acc[i][7]);
        float pS = 0.0f, pD = 0.0f;
        #pragma unroll
        for (int j = 0; j < 8; j++) {
            pS += acc[i][j] * sS[tx * 8 + j];
            pD += acc[i][j] * sD[tx * 8 + j];
        }
        pS += __shfl_xor_sync(0xffffffffu, pS, 1);
        pS += __shfl_xor_sync(0xffffffffu, pS, 2);
        pS += __shfl_xor_sync(0xffffffffu, pS, 4);
        pD += __shfl_xor_sync(0xffffffffu, pD, 1);
        pD += __shfl_xor_sync(0xffffffffu, pD, 2);
        pD += __shfl_xor_sync(0xffffffffu, pD, 4);
        if ((tx & 7) == 0) {
            int hd = tx >> 3;
            aS[row * 4 + hd] = pS;
            aD[row * 4 + hd] = pD;
        }
    }
}

// ---------------- fused segment softmax + weighted aggregate ------------------
__device__ __forceinline__ float lrelu(float v) { return v > 0.0f ? v : 0.2f * v; }

__global__ void k_aggregate(const int* __restrict__ rowptr, const int* __restrict__ csrc,
                            const float* __restrict__ H, const float* __restrict__ aS,
                            const float* __restrict__ aD, const float* __restrict__ bias,
                            float* __restrict__ ex, float* __restrict__ out) {
    int warp = (blockIdx.x * blockDim.x + threadIdx.x) >> 5;
    int lane = threadIdx.x & 31;
    if (warp >= NNODE) return;
    int rs = rowptr[warp], re = rowptr[warp + 1];
    float4 ad = *(const float4*)(aD + warp * 4);

    float m0 = -1e30f, m1 = -1e30f, m2 = -1e30f, m3 = -1e30f;
    for (int e = rs + lane; e < re; e += 32) {
        int s = csrc[e];
        float4 as = *(const float4*)(aS + s * 4);
        m0 = fmaxf(m0, lrelu(as.x + ad.x));
        m1 = fmaxf(m1, lrelu(as.y + ad.y));
        m2 = fmaxf(m2, lrelu(as.z + ad.z));
        m3 = fmaxf(m3, lrelu(as.w + ad.w));
    }
    #pragma unroll
    for (int o = 16; o > 0; o >>= 1) {
        m0 = fmaxf(m0, __shfl_xor_sync(0xffffffffu, m0, o));
        m1 = fmaxf(m1, __shfl_xor_sync(0xffffffffu, m1, o));
        m2 = fmaxf(m2, __shfl_xor_sync(0xffffffffu, m2, o));
        m3 = fmaxf(m3, __shfl_xor_sync(0xffffffffu, m3, o));
    }
    float s0 = 0, s1 = 0, s2 = 0, s3 = 0;
    for (int e = rs + lane; e < re; e += 32) {
        int s = csrc[e];
        float4 as = *(const float4*)(aS + s * 4);
        float x0 = expf(lrelu(as.x + ad.x) - m0);
        float x1 = expf(lrelu(as.y + ad.y) - m1);
        float x2 = expf(lrelu(as.z + ad.z) - m2);
        float x3 = expf(lrelu(as.w + ad.w) - m3);
        *(float4*)(ex + e * 4) = make_float4(x0, x1, x2, x3);
        s0 += x0; s1 += x1; s2 += x2; s3 += x3;
    }
    #pragma unroll
    for (int o = 16; o > 0; o >>= 1) {
        s0 += __shfl_xor_sync(0xffffffffu, s0, o);
        s1 += __shfl_xor_sync(0xffffffffu, s1, o);
        s2 += __shfl_xor_sync(0xffffffffu, s2, o);
        s3 += __shfl_xor_sync(0xffffffffu, s3, o);
    }
    int head = lane >> 3;
    float sh = head == 0 ? s0 : head == 1 ? s1 : head == 2 ? s2 : s3;
    float inv = 1.0f / (sh + 1e-16f);

    float acc[8] = {};
    int sNext = csrc[rs];
    for (int e = rs; e < re; e++) {
        int s = sNext;
        if (e + 1 < re) sNext = csrc[e + 1];
        float alpha = __ldg(ex + e * 4 + head) * inv;
        const float4* hp = (const float4*)(H + s * DMODEL + lane * 8);
        float4 h0 = hp[0], h1 = hp[1];
        acc[0] += alpha * h0.x; acc[1] += alpha * h0.y;
        acc[2] += alpha * h0.z; acc[3] += alpha * h0.w;
        acc[4] += alpha * h1.x; acc[5] += alpha * h1.y;
        acc[6] += alpha * h1.z; acc[7] += alpha * h1.w;
    }
    const float4* bp = (const float4*)(bias + lane * 8);
    float4 b0 = bp[0], b1 = bp[1];
    float r[8];
    r[0] = acc[0] + b0.x; r[1] = acc[1] + b0.y; r[2] = acc[2] + b0.z; r[3] = acc[3] + b0.w;
    r[4] = acc[4] + b1.x; r[5] = acc[5] + b1.y; r[6] = acc[6] + b1.z; r[7] = acc[7] + b1.w;
    #pragma unroll
    for (int i = 0; i < 8; i++) r[i] = r[i] > 0.0f ? r[i] : 0.0f;
    float* op = out + warp * DMODEL + lane * 8;
    *(float4*)op       = make_float4(r[0], r[1], r[2], r[3]);
    *(float4*)(op + 4) = make_float4(r[4], r[5], r[6], r[7]);
}

// ---------------- epilogue -----------------------------------------------------
#define FB 64
__global__ void __launch_bounds__(256)
k_final(const float* __restrict__ X, const float* __restrict__ Wg,
        const float* __restrict__ bg, const float* __restrict__ Wf,
        const float* __restrict__ bf, float* __restrict__ out) {
    __shared__ float sWg[64][FEAT];
    __shared__ float sy[FB][FEAT + 1];
    __shared__ float sWf[FEAT * 5];

    int tid = threadIdx.x;
    int node0 = blockIdx.x * FB;
    int nodeL = tid >> 2;
    int f0 = (tid & 3) * 16;

    for (int i = tid; i < FEAT * 5; i += 256) sWf[i] = Wf[i];

    float acc[16];
    {
        float4 g0 = *(const float4*)(bg + f0);
        float4 g1 = *(const float4*)(bg + f0 + 4);
        float4 g2 = *(const float4*)(bg + f0 + 8);
        float4 g3 = *(const float4*)(bg + f0 + 12);
        acc[0] = g0.x; acc[1] = g0.y; acc[2] = g0.z; acc[3] = g0.w;
        acc[4] = g1.x; acc[5] = g1.y; acc[6] = g1.z; acc[7] = g1.w;
        acc[8] = g2.x; acc[9] = g2.y; acc[10] = g2.z; acc[11] = g2.w;
        acc[12] = g3.x; acc[13] = g3.y; acc[14] = g3.z; acc[15] = g3.w;
    }

    const float* xr = X + (node0 + nodeL) * DMODEL;
    #pragma unroll 1
    for (int kc = 0; kc < DMODEL; kc += 64) {
        #pragma unroll
        for (int t = 0; t < 4; t++) {
            int idx = (tid + t * 256) * 4;
            *(float4*)&sWg[idx >> 6][idx & 63] = *(const float4*)(Wg + (kc << 6) + idx);
        }
        __syncthreads();
        #pragma unroll
        for (int k4 = 0; k4 < 16; k4++) {
            float4 xv = *(const float4*)(xr + kc + k4 * 4);
            #pragma unroll
            for (int kk = 0; kk < 4; kk++) {
                float x = kk == 0 ? xv.x : kk == 1 ? xv.y : kk == 2 ? xv.z : xv.w;
                const float* wrow = &sWg[k4 * 4 + kk][f0];
                float4 w0 = *(const float4*)(wrow);
                float4 w1 = *(const float4*)(wrow + 4);
                float4 w2 = *(const float4*)(wrow + 8);
                float4 w3 = *(const float4*)(wrow + 12);
                acc[0] += x * w0.x; acc[1] += x * w0.y; acc[2] += x * w0.z; acc[3] += x * w0.w;
                acc[4] += x * w1.x; acc[5] += x * w1.y; acc[6] += x * w1.z; acc[7] += x * w1.w;
                acc[8] += x * w2.x; acc[9] += x * w2.y; acc[10] += x * w2.z; acc[11] += x * w2.w;
                acc[12] += x * w3.x; acc[13] += x * w3.y; acc[14] += x * w3.z; acc[15] += x * w3.w;
            }
        }
        __syncthreads();
    }
    #pragma unroll
    for (int j = 0; j < 16; j++) {
        float v = acc[j];
        sy[nodeL][f0 + j] = v > 0.0f ? v : 0.0f;
    }
    __syncthreads();

    for (int idx = tid; idx < FB * 5; idx += 256) {
        int n = idx / 5, c = idx % 5;
        float o = bf[c];
        #pragma unroll
        for (int k = 0; k < FEAT; k++) o += sy[n][k] * sWf[k * 5 + c];
        out[(node0 + n) * 5 + c] = o;
    }
}

// ---------------- host orchestration ------------------------------------------
extern "C" void kernel_launch(void* const* d_in, const int* in_sizes, int n_in,
                              void* d_out, int out_size) {
    const float* z     = (const float*)d_in[0];
    const int*   ei    = (const int*)d_in[1];
    const int*   batch = (const int*)d_in[2];
    int base = (in_sizes[3] == 1) ? 4 : 3;
    const float* W0  = (const float*)d_in[base + 0];
    const float* b0  = (const float*)d_in[base + 1];
    const float* W1  = (const float*)d_in[base + 2];
    const float* as1 = (const float*)d_in[base + 3];
    const float* ad1 = (const float*)d_in[base + 4];
    const float* bb1 = (const float*)d_in[base + 5];
    const float* W2  = (const float*)d_in[base + 6];
    const float* as2 = (const float*)d_in[base + 7];
    const float* ad2 = (const float*)d_in[base + 8];
    const float* bb2 = (const float*)d_in[base + 9];
    const float* W3  = (const float*)d_in[base + 10];
    const float* as3 = (const float*)d_in[base + 11];
    const float* ad3 = (const float*)d_in[base + 12];
    const float* bb3 = (const float*)d_in[base + 13];
    const float* Wg  = (const float*)d_in[base + 14];
    const float* bg  = (const float*)d_in[base + 15];
    const float* Wf  = (const float*)d_in[base + 16];
    const float* bf  = (const float*)d_in[base + 17];

    const int N = NNODE;
    const int* srcArr = ei;
    const int* dstArr = ei + NEDGE;

    float *bufA, *bufB, *aS, *aD, *exB, *pgB;
    int *startsB, *degB, *rowptrB, *cursorB, *csrcB;
    cudaGetSymbolAddress((void**)&bufA, g_bufA);
    cudaGetSymbolAddress((void**)&bufB, g_bufB);
    cudaGetSymbolAddress((void**)&aS, g_as);
    cudaGetSymbolAddress((void**)&aD, g_ad);
    cudaGetSymbolAddress((void**)&exB, g_ex);
    cudaGetSymbolAddress((void**)&pgB, g_pg);
    cudaGetSymbolAddress((void**)&startsB, g_starts);
    cudaGetSymbolAddress((void**)&degB, g_deg);
    cudaGetSymbolAddress((void**)&rowptrB, g_rowptr);
    cudaGetSymbolAddress((void**)&cursorB, g_cursor);
    cudaGetSymbolAddress((void**)&csrcB, g_csrc);

    int warpBlocks = (N + 7) / 8;

    // 1: fused x0 + pg
    k_x0pg<<<NGRAPH, 256>>>(z, W0, b0, W1, pgB);
    // 2: fused starts + deg init
    k_prep<<<(N + 255) / 256, 256>>>(batch, startsB, degB, N);
    // 3: degree histogram
    k_hist<<<(NEDGE + 255) / 256, 256>>>(dstArr, degB);
    // 4: fused scan + self-loop fill
    k_scan_fill<<<1, 1024>>>(degB, rowptrB, cursorB, csrcB);
    // 5: CSR scatter
    k_scatter<<<(NEDGE + 255) / 256, 256>>>(srcArr, dstArr, cursorB, csrcB);
    // 6: fused h1 + attention logits (layer 1)
    k_h1attn<<<warpBlocks, 256>>>(pgB, W1, batch, startsB, as1, ad1, bufB, aS, aD, N);
    // 7: aggregate layer 1
    k_aggregate<<<warpBlocks, 256>>>(rowptrB, csrcB, bufB, aS, aD, bb1, exB, bufA);
    // 8-11: layers 2,3 (fused gemm+attn, aggregate)
    k_gemm_attn<<<N / GBM, 512>>>(bufA, W2, as2, ad2, bufB, aS, aD);
    k_aggregate<<<warpBlocks, 256>>>(rowptrB, csrcB, bufB, aS, aD, bb2, exB, bufA);
    k_gemm_attn<<<N / GBM, 512>>>(bufA, W3, as3, ad3, bufB, aS, aD);
    k_aggregate<<<warpBlocks, 256>>>(rowptrB, csrcB, bufB, aS, aD, bb3, exB, bufA);
    // 12: epilogue
    k_final<<<N / FB, 256>>>(bufA, Wg, bg, Wf, bf, (float*)d_out);
}

// round 5
// speedup vs baseline: 4.9762x; 1.2421x over previous
#include <cuda_runtime.h>
#include <math.h>
#include <stdint.h>

// ---------------- problem constants -----------------------------------------
#define NNODE 19200
#define NEDGE 230400
#define NGRAPH 128
#define LATENT 256
#define FEAT 64
#define HEADS 4
#define POS 180
#define DMODEL 256       // HEADS * FEAT
#define ETOT (NEDGE + NNODE)
#define NBLK 75          // NNODE / 256

// ---------------- static device scratch --------------------------------------
__device__ __align__(16) float g_bufA[NNODE * DMODEL];
__device__ __align__(16) float g_bufB[NNODE * DMODEL];
__device__ __align__(16) float g_as[NNODE * HEADS];
__device__ __align__(16) float g_ad[NNODE * HEADS];
__device__ __align__(16) float g_ex[ETOT * HEADS];
__device__ __align__(16) float g_pg[NGRAPH * DMODEL];
__device__ int g_starts[NGRAPH];
__device__ int g_deg[NNODE];
__device__ int g_bsum[NBLK];
__device__ int g_rowptr[NNODE + 1];
__device__ int g_cursor[NNODE];
__device__ int g_csrc[ETOT];

// ---------------- fused prologue: x0 = relu(z@W0+b0); pg = x0@W1[:64] ---------
__global__ void k_x0pg(const float* __restrict__ z, const float* __restrict__ W0,
                       const float* __restrict__ b0, const float* __restrict__ W1,
                       float* __restrict__ pg) {
    __shared__ float xs[FEAT];
    int g = blockIdx.x, t = threadIdx.x;
    if (t < FEAT) {
        float acc = b0[t];
        const float* zr = z + g * LATENT;
        #pragma unroll 4
        for (int k = 0; k < LATENT; k++) acc += zr[k] * W0[k * FEAT + t];
        xs[t] = acc > 0.0f ? acc : 0.0f;
    }
    __syncthreads();
    float a = 0.0f;
    #pragma unroll
    for (int k = 0; k < FEAT; k++) a += xs[k] * W1[k * DMODEL + t];
    pg[g * DMODEL + t] = a;
}

// ---------------- CSR build ----------------------------------------------------
__global__ void k_prep(const int* __restrict__ batch, int* __restrict__ starts,
                       int* __restrict__ deg, int N) {
    int i = blockIdx.x * blockDim.x + threadIdx.x;
    if (i >= N) return;
    int b = batch[i];
    if (i == 0 || batch[i - 1] != b) starts[b] = i;
    deg[i] = 1;
}

__global__ void k_hist(const int* __restrict__ dst, int* __restrict__ deg) {
    int e = blockIdx.x * blockDim.x + threadIdx.x;
    if (e < NEDGE) atomicAdd(&deg[dst[e]], 1);
}

// per-256-node block sums
__global__ void k_bsum(const int* __restrict__ deg, int* __restrict__ bsum) {
    __shared__ int s[256];
    int t = threadIdx.x;
    s[t] = deg[blockIdx.x * 256 + t];
    __syncthreads();
    for (int off = 128; off > 0; off >>= 1) {
        if (t < off) s[t] += s[t + off];
        __syncthreads();
    }
    if (t == 0) bsum[blockIdx.x] = s[0];
}

// per-block: compute boff (reduce over bsum[<b]) + local scan + fill
__global__ void k_fill(const int* __restrict__ deg, const int* __restrict__ bsum,
                       int* __restrict__ rowptr, int* __restrict__ cursor,
                       int* __restrict__ csrc) {
    __shared__ int s[256];
    __shared__ int red[128];
    int t = threadIdx.x;
    int b = blockIdx.x;
    // boff = sum of bsum[0..b-1]
    int v = 0;
    if (t < NBLK && t < b) v = bsum[t];
    if (t < 128) red[t] = v;
    __syncthreads();
    if (t < 128) {
        for (int off = 64; off > 0; off >>= 1) {
            if (t < off) red[t] += red[t + off];
            __syncthreads();
        }
    } else {
        for (int off = 64; off > 0; off >>= 1) __syncthreads();
    }
    int node = b * 256 + t;
    int d = deg[node];
    s[t] = d;
    __syncthreads();
    // inclusive Hillis-Steele scan
    for (int off = 1; off < 256; off <<= 1) {
        int u = (t >= off) ? s[t - off] : 0;
        __syncthreads();
        s[t] += u;
        __syncthreads();
    }
    int r = red[0] + s[t] - d;                // exclusive
    rowptr[node] = r;
    csrc[r] = node;                           // self loop first
    cursor[node] = r + 1;
    if (node == NNODE - 1) rowptr[NNODE] = red[0] + s[t];
}

__global__ void k_scatter(const int* __restrict__ src, const int* __restrict__ dst,
                          int* __restrict__ cursor, int* __restrict__ csrc) {
    int e = blockIdx.x * blockDim.x + threadIdx.x;
    if (e >= NEDGE) return;
    int p = atomicAdd(&cursor[dst[e]], 1);
    csrc[p] = src[e];
}

// ---------------- fused: h1 build + attention logits ---------------------------
__global__ void k_h1attn(const float* __restrict__ pg, const float* __restrict__ W1,
                         const int* __restrict__ batch, const int* __restrict__ starts,
                         const float* __restrict__ attS, const float* __restrict__ attD,
                         float* __restrict__ H, float* __restrict__ aS,
                         float* __restrict__ aD, int N) {
    __shared__ float sS[DMODEL], sD[DMODEL];
    int tid = threadIdx.x;
    if (tid < DMODEL) { sS[tid] = attS[tid]; sD[tid] = attD[tid]; }
    __syncthreads();
    int node = (blockIdx.x * blockDim.x + tid) >> 5;
    int lane = tid & 31;
    if (node >= N) return;
    int g = batch[node];
    int order = node - starts[g];
    int c0 = lane * 8;
    const float4* pgr = (const float4*)(pg + g * DMODEL + c0);
    const float4* w1r = (const float4*)(W1 + (FEAT + order) * DMODEL + c0);
    float4 p0 = pgr[0], p1 = pgr[1];
    float4 w0 = w1r[0], w1v = w1r[1];
    float h[8];
    h[0] = p0.x + w0.x; h[1] = p0.y + w0.y; h[2] = p0.z + w0.z; h[3] = p0.w + w0.w;
    h[4] = p1.x + w1v.x; h[5] = p1.y + w1v.y; h[6] = p1.z + w1v.z; h[7] = p1.w + w1v.w;
    float* hr = H + node * DMODEL + c0;
    *(float4*)hr       = make_float4(h[0], h[1], h[2], h[3]);
    *(float4*)(hr + 4) = make_float4(h[4], h[5], h[6], h[7]);
    float pS = 0.0f, pD = 0.0f;
    #pragma unroll
    for (int j = 0; j < 8; j++) { pS += h[j] * sS[c0 + j]; pD += h[j] * sD[c0 + j]; }
    pS += __shfl_xor_sync(0xffffffffu, pS, 1);
    pS += __shfl_xor_sync(0xffffffffu, pS, 2);
    pS += __shfl_xor_sync(0xffffffffu, pS, 4);
    pD += __shfl_xor_sync(0xffffffffu, pD, 1);
    pD += __shfl_xor_sync(0xffffffffu, pD, 2);
    pD += __shfl_xor_sync(0xffffffffu, pD, 4);
    if ((lane & 7) == 0) {
        int hd = lane >> 3;
        aS[node * 4 + hd] = pS;
        aD[node * 4 + hd] = pD;
    }
}

// ---------------- tf32 tensor-core GEMM + fused attention logits ---------------
// C[19200,256] = X @ W.  Tile 128x128, grid (150, 2), 256 threads (8 warps).
// Warp tile 64x32 (wm in 0..1, wn in 0..3). mma.m16n8k8.tf32.
#define SMS 136   // smem row stride (conflict-free: 136 mod 32 = 8)

__device__ __forceinline__ uint32_t f2tf32(float v) {
    uint32_t r;
    asm("cvt.rna.tf32.f32 %0, %1;" : "=r"(r) : "f"(v));
    return r;
}
__device__ __forceinline__ void mma_tf32(float* c, uint32_t a0, uint32_t a1,
                                         uint32_t a2, uint32_t a3,
                                         uint32_t b0, uint32_t b1) {
    asm volatile(
        "mma.sync.aligned.m16n8k8.row.col.f32.tf32.tf32.f32 "
        "{%0,%1,%2,%3}, {%4,%5,%6,%7}, {%8,%9}, {%0,%1,%2,%3};"
        : "+f"(c[0]), "+f"(c[1]), "+f"(c[2]), "+f"(c[3])
        : "r"(a0), "r"(a1), "r"(a2), "r"(a3), "r"(b0), "r"(b1));
}

__global__ void __launch_bounds__(256, 1)
k_gemm_attn(const float* __restrict__ X, const float* __restrict__ W,
            const float* __restrict__ attS, const float* __restrict__ attD,
            float* __restrict__ C, float* __restrict__ aS, float* __restrict__ aD) {
    __shared__ uint32_t As[32][SMS];     // [k][m], tf32 bits
    __shared__ uint32_t Bs[32][SMS];     // [k][n]
    __shared__ float sS[128], sD[128];
    __shared__ float sPS[128][2], sPD[128][2];

    int tid = threadIdx.x;
    int lane = tid & 31;
    int w = tid >> 5;
    int wm = w & 1, wn = w >> 1;
    int r0 = blockIdx.x * 128;
    int c0 = blockIdx.y * 128;

    if (tid < 128) { sS[tid] = attS[c0 + tid]; sD[tid] = attD[c0 + tid]; }
    {   // zero partial arrays (256 entries each)
        int rr = tid >> 1, hh = tid & 1;
        sPS[rr][hh] = 0.0f;
        sPD[rr][hh] = 0.0f;
    }

    float acc[4][4][4];
    #pragma unroll
    for (int i = 0; i < 4; i++)
        #pragma unroll
        for (int j = 0; j < 4; j++)
            #pragma unroll
            for (int q = 0; q < 4; q++) acc[i][j][q] = 0.0f;

    // loader indices
    int am = tid >> 1;                    // 0..127 row of A
    int ak = (tid & 1) * 16;              // k base (16 floats)
    int bkr = tid >> 3;                   // 0..31 k row of B
    int bn = (tid & 7) * 16;              // n base (16 floats)

    #pragma unroll 1
    for (int kc = 0; kc < DMODEL; kc += 32) {
        // load A chunk: X[r0+am][kc+ak .. +15]
        const float4* ap = (const float4*)(X + (r0 + am) * DMODEL + kc + ak);
        #pragma unroll
        for (int q = 0; q < 4; q++) {
            float4 v = ap[q];
            As[ak + q * 4 + 0][am] = f2tf32(v.x);
            As[ak + q * 4 + 1][am] = f2tf32(v.y);
            As[ak + q * 4 + 2][am] = f2tf32(v.z);
            As[ak + q * 4 + 3][am] = f2tf32(v.w);
        }
        // load B chunk: W[kc+bkr][c0+bn .. +15]
        const float4* bp = (const float4*)(W + (kc + bkr) * DMODEL + c0 + bn);
        #pragma unroll
        for (int q = 0; q < 4; q++) {
            float4 v = bp[q];
            uint4 u;
            u.x = f2tf32(v.x); u.y = f2tf32(v.y);
            u.z = f2tf32(v.z); u.w = f2tf32(v.w);
            *(uint4*)&Bs[bkr][bn + q * 4] = u;
        }
        __syncthreads();

        #pragma unroll
        for (int kk = 0; kk < 4; kk++) {
            int kb = kk * 8;
            int klo = kb + (lane & 3), khi = klo + 4;
            uint32_t afr[4][4], bfr[4][2];
            #pragma unroll
            for (int mt = 0; mt < 4; mt++) {
                int m = wm * 64 + mt * 16 + (lane >> 2);
                afr[mt][0] = As[klo][m];
                afr[mt][1] = As[klo][m + 8];
                afr[mt][2] = As[khi][m];
                afr[mt][3] = As[khi][m + 8];
            }
            #pragma unroll
            for (int nt = 0; nt < 4; nt++) {
                int n = wn * 32 + nt * 8 + (lane >> 2);
                bfr[nt][0] = Bs[klo][n];
                bfr[nt][1] = Bs[khi][n];
            }
            #pragma unroll
            for (int mt = 0; mt < 4; mt++)
                #pragma unroll
                for (int nt = 0; nt < 4; nt++)
                    mma_tf32(acc[mt][nt], afr[mt][0], afr[mt][1], afr[mt][2],
                             afr[mt][3], bfr[nt][0], bfr[nt][1]);
        }
        __syncthreads();
    }

    // ---- epilogue: store C and fused attention partials ----
    int hb = wn >> 1;                       // head within block (0/1)
    #pragma unroll
    for (int mt = 0; mt < 4; mt++) {
        int rowA = wm * 64 + mt * 16 + (lane >> 2);
        int rowB = rowA + 8;
        float pSa = 0.0f, pDa = 0.0f, pSb = 0.0f, pDb = 0.0f;
        #pragma unroll
        for (int nt = 0; nt < 4; nt++) {
            int lc = wn * 32 + nt * 8 + 2 * (lane & 3);
            float s0 = sS[lc], s1 = sS[lc + 1];
            float d0 = sD[lc], d1 = sD[lc + 1];
            float* a = acc[mt][nt];
            pSa += a[0] * s0 + a[1] * s1;
            pDa += a[0] * d0 + a[1] * d1;
            pSb += a[2] * s0 + a[3] * s1;
            pDb += a[2] * d0 + a[3] * d1;
            // store C
            float* cpA = C + (r0 + rowA) * DMODEL + c0 + lc;
            float* cpB = C + (r0 + rowB) * DMODEL + c0 + lc;
            *(float2*)cpA = make_float2(a[0], a[1]);
            *(float2*)cpB = make_float2(a[2], a[3]);
        }
        // reduce over the 4 lanes of the quad (lane&3)
        pSa += __shfl_xor_sync(0xffffffffu, pSa, 1);
        pSa += __shfl_xor_sync(0xffffffffu, pSa, 2);
        pDa += __shfl_xor_sync(0xffffffffu, pDa, 1);
        pDa += __shfl_xor_sync(0xffffffffu, pDa, 2);
        pSb += __shfl_xor_sync(0xffffffffu, pSb, 1);
        pSb += __shfl_xor_sync(0xffffffffu, pSb, 2);
        pDb += __shfl_xor_sync(0xffffffffu, pDb, 1);
        pDb += __shfl_xor_sync(0xffffffffu, pDb, 2);
        if ((lane & 3) == 0) {
            atomicAdd(&sPS[rowA][hb], pSa);
            atomicAdd(&sPD[rowA][hb], pDa);
            atomicAdd(&sPS[rowB][hb], pSb);
            atomicAdd(&sPD[rowB][hb], pDb);
        }
    }
    __syncthreads();
    {
        int rr = tid >> 1, hh = tid & 1;
        int node = r0 + rr;
        int head = blockIdx.y * 2 + hh;
        aS[node * 4 + head] = sPS[rr][hh];
        aD[node * 4 + head] = sPD[rr][hh];
    }
}

// ---------------- fused segment softmax + weighted aggregate ------------------
__device__ __forceinline__ float lrelu(float v) { return v > 0.0f ? v : 0.2f * v; }

__global__ void k_aggregate(const int* __restrict__ rowptr, const int* __restrict__ csrc,
                            const float* __restrict__ H, const float* __restrict__ aS,
                            const float* __restrict__ aD, const float* __restrict__ bias,
                            float* __restrict__ ex, float* __restrict__ out) {
    int warp = (blockIdx.x * blockDim.x + threadIdx.x) >> 5;
    int lane = threadIdx.x & 31;
    if (warp >= NNODE) return;
    int rs = rowptr[warp], re = rowptr[warp + 1];
    float4 ad = *(const float4*)(aD + warp * 4);

    float m0 = -1e30f, m1 = -1e30f, m2 = -1e30f, m3 = -1e30f;
    for (int e = rs + lane; e < re; e += 32) {
        int s = csrc[e];
        float4 as = *(const float4*)(aS + s * 4);
        m0 = fmaxf(m0, lrelu(as.x + ad.x));
        m1 = fmaxf(m1, lrelu(as.y + ad.y));
        m2 = fmaxf(m2, lrelu(as.z + ad.z));
        m3 = fmaxf(m3, lrelu(as.w + ad.w));
    }
    #pragma unroll
    for (int o = 16; o > 0; o >>= 1) {
        m0 = fmaxf(m0, __shfl_xor_sync(0xffffffffu, m0, o));
        m1 = fmaxf(m1, __shfl_xor_sync(0xffffffffu, m1, o));
        m2 = fmaxf(m2, __shfl_xor_sync(0xffffffffu, m2, o));
        m3 = fmaxf(m3, __shfl_xor_sync(0xffffffffu, m3, o));
    }
    float s0 = 0, s1 = 0, s2 = 0, s3 = 0;
    for (int e = rs + lane; e < re; e += 32) {
        int s = csrc[e];
        float4 as = *(const float4*)(aS + s * 4);
        float x0 = expf(lrelu(as.x + ad.x) - m0);
        float x1 = expf(lrelu(as.y + ad.y) - m1);
        float x2 = expf(lrelu(as.z + ad.z) - m2);
        float x3 = expf(lrelu(as.w + ad.w) - m3);
        *(float4*)(ex + e * 4) = make_float4(x0, x1, x2, x3);
        s0 += x0; s1 += x1; s2 += x2; s3 += x3;
    }
    #pragma unroll
    for (int o = 16; o > 0; o >>= 1) {
        s0 += __shfl_xor_sync(0xffffffffu, s0, o);
        s1 += __shfl_xor_sync(0xffffffffu, s1, o);
        s2 += __shfl_xor_sync(0xffffffffu, s2, o);
        s3 += __shfl_xor_sync(0xffffffffu, s3, o);
    }
    int head = lane >> 3;
    float sh = head == 0 ? s0 : head == 1 ? s1 : head == 2 ? s2 : s3;
    float inv = 1.0f / (sh + 1e-16f);

    float acc[8] = {};
    int sNext = csrc[rs];
    for (int e = rs; e < re; e++) {
        int s = sNext;
        if (e + 1 < re) sNext = csrc[e + 1];
        float alpha = __ldg(ex + e * 4 + head) * inv;
        const float4* hp = (const float4*)(H + s * DMODEL + lane * 8);
        float4 h0 = hp[0], h1 = hp[1];
        acc[0] += alpha * h0.x; acc[1] += alpha * h0.y;
        acc[2] += alpha * h0.z; acc[3] += alpha * h0.w;
        acc[4] += alpha * h1.x; acc[5] += alpha * h1.y;
        acc[6] += alpha * h1.z; acc[7] += alpha * h1.w;
    }
    const float4* bp = (const float4*)(bias + lane * 8);
    float4 b0 = bp[0], b1 = bp[1];
    float r[8];
    r[0] = acc[0] + b0.x; r[1] = acc[1] + b0.y; r[2] = acc[2] + b0.z; r[3] = acc[3] + b0.w;
    r[4] = acc[4] + b1.x; r[5] = acc[5] + b1.y; r[6] = acc[6] + b1.z; r[7] = acc[7] + b1.w;
    #pragma unroll
    for (int i = 0; i < 8; i++) r[i] = r[i] > 0.0f ? r[i] : 0.0f;
    float* op = out + warp * DMODEL + lane * 8;
    *(float4*)op       = make_float4(r[0], r[1], r[2], r[3]);
    *(float4*)(op + 4) = make_float4(r[4], r[5], r[6], r[7]);
}

// ---------------- epilogue -----------------------------------------------------
#define FB 64
__global__ void __launch_bounds__(256)
k_final(const float* __restrict__ X, const float* __restrict__ Wg,
        const float* __restrict__ bg, const float* __restrict__ Wf,
        const float* __restrict__ bf, float* __restrict__ out) {
    __shared__ float sWg[64][FEAT];
    __shared__ float sy[FB][FEAT + 1];
    __shared__ float sWf[FEAT * 5];

    int tid = threadIdx.x;
    int node0 = blockIdx.x * FB;
    int nodeL = tid >> 2;
    int f0 = (tid & 3) * 16;

    for (int i = tid; i < FEAT * 5; i += 256) sWf[i] = Wf[i];

    float acc[16];
    {
        float4 g0 = *(const float4*)(bg + f0);
        float4 g1 = *(const float4*)(bg + f0 + 4);
        float4 g2 = *(const float4*)(bg + f0 + 8);
        float4 g3 = *(const float4*)(bg + f0 + 12);
        acc[0] = g0.x; acc[1] = g0.y; acc[2] = g0.z; acc[3] = g0.w;
        acc[4] = g1.x; acc[5] = g1.y; acc[6] = g1.z; acc[7] = g1.w;
        acc[8] = g2.x; acc[9] = g2.y; acc[10] = g2.z; acc[11] = g2.w;
        acc[12] = g3.x; acc[13] = g3.y; acc[14] = g3.z; acc[15] = g3.w;
    }

    const float* xr = X + (node0 + nodeL) * DMODEL;
    #pragma unroll 1
    for (int kc = 0; kc < DMODEL; kc += 64) {
        #pragma unroll
        for (int t = 0; t < 4; t++) {
            int idx = (tid + t * 256) * 4;
            *(float4*)&sWg[idx >> 6][idx & 63] = *(const float4*)(Wg + (kc << 6) + idx);
        }
        __syncthreads();
        #pragma unroll
        for (int k4 = 0; k4 < 16; k4++) {
            float4 xv = *(const float4*)(xr + kc + k4 * 4);
            #pragma unroll
            for (int kk = 0; kk < 4; kk++) {
                float x = kk == 0 ? xv.x : kk == 1 ? xv.y : kk == 2 ? xv.z : xv.w;
                const float* wrow = &sWg[k4 * 4 + kk][f0];
                float4 w0 = *(const float4*)(wrow);
                float4 w1 = *(const float4*)(wrow + 4);
                float4 w2 = *(const float4*)(wrow + 8);
                float4 w3 = *(const float4*)(wrow + 12);
                acc[0] += x * w0.x; acc[1] += x * w0.y; acc[2] += x * w0.z; acc[3] += x * w0.w;
                acc[4] += x * w1.x; acc[5] += x * w1.y; acc[6] += x * w1.z; acc[7] += x * w1.w;
                acc[8] += x * w2.x; acc[9] += x * w2.y; acc[10] += x * w2.z; acc[11] += x * w2.w;
                acc[12] += x * w3.x; acc[13] += x * w3.y; acc[14] += x * w3.z; acc[15] += x * w3.w;
            }
        }
        __syncthreads();
    }
    #pragma unroll
    for (int j = 0; j < 16; j++) {
        float v = acc[j];
        sy[nodeL][f0 + j] = v > 0.0f ? v : 0.0f;
    }
    __syncthreads();

    for (int idx = tid; idx < FB * 5; idx += 256) {
        int n = idx / 5, c = idx % 5;
        float o = bf[c];
        #pragma unroll
        for (int k = 0; k < FEAT; k++) o += sy[n][k] * sWf[k * 5 + c];
        out[(node0 + n) * 5 + c] = o;
    }
}

// ---------------- host orchestration ------------------------------------------
extern "C" void kernel_launch(void* const* d_in, const int* in_sizes, int n_in,
                              void* d_out, int out_size) {
    const float* z     = (const float*)d_in[0];
    const int*   ei    = (const int*)d_in[1];
    const int*   batch = (const int*)d_in[2];
    int base = (in_sizes[3] == 1) ? 4 : 3;
    const float* W0  = (const float*)d_in[base + 0];
    const float* b0  = (const float*)d_in[base + 1];
    const float* W1  = (const float*)d_in[base + 2];
    const float* as1 = (const float*)d_in[base + 3];
    const float* ad1 = (const float*)d_in[base + 4];
    const float* bb1 = (const float*)d_in[base + 5];
    const float* W2  = (const float*)d_in[base + 6];
    const float* as2 = (const float*)d_in[base + 7];
    const float* ad2 = (const float*)d_in[base + 8];
    const float* bb2 = (const float*)d_in[base + 9];
    const float* W3  = (const float*)d_in[base + 10];
    const float* as3 = (const float*)d_in[base + 11];
    const float* ad3 = (const float*)d_in[base + 12];
    const float* bb3 = (const float*)d_in[base + 13];
    const float* Wg  = (const float*)d_in[base + 14];
    const float* bg  = (const float*)d_in[base + 15];
    const float* Wf  = (const float*)d_in[base + 16];
    const float* bf  = (const float*)d_in[base + 17];

    const int N = NNODE;
    const int* srcArr = ei;
    const int* dstArr = ei + NEDGE;

    float *bufA, *bufB, *aS, *aD, *exB, *pgB;
    int *startsB, *degB, *bsumB, *rowptrB, *cursorB, *csrcB;
    cudaGetSymbolAddress((void**)&bufA, g_bufA);
    cudaGetSymbolAddress((void**)&bufB, g_bufB);
    cudaGetSymbolAddress((void**)&aS, g_as);
    cudaGetSymbolAddress((void**)&aD, g_ad);
    cudaGetSymbolAddress((void**)&exB, g_ex);
    cudaGetSymbolAddress((void**)&pgB, g_pg);
    cudaGetSymbolAddress((void**)&startsB, g_starts);
    cudaGetSymbolAddress((void**)&degB, g_deg);
    cudaGetSymbolAddress((void**)&bsumB, g_bsum);
    cudaGetSymbolAddress((void**)&rowptrB, g_rowptr);
    cudaGetSymbolAddress((void**)&cursorB, g_cursor);
    cudaGetSymbolAddress((void**)&csrcB, g_csrc);

    int warpBlocks = (N + 7) / 8;
    dim3 gemmGrid(N / 128, 2);

    k_x0pg<<<NGRAPH, 256>>>(z, W0, b0, W1, pgB);
    k_prep<<<(N + 255) / 256, 256>>>(batch, startsB, degB, N);
    k_hist<<<(NEDGE + 255) / 256, 256>>>(dstArr, degB);
    k_bsum<<<NBLK, 256>>>(degB, bsumB);
    k_fill<<<NBLK, 256>>>(degB, bsumB, rowptrB, cursorB, csrcB);
    k_scatter<<<(NEDGE + 255) / 256, 256>>>(srcArr, dstArr, cursorB, csrcB);

    k_h1attn<<<warpBlocks, 256>>>(pgB, W1, batch, startsB, as1, ad1, bufB, aS, aD, N);
    k_aggregate<<<warpBlocks, 256>>>(rowptrB, csrcB, bufB, aS, aD, bb1, exB, bufA);

    k_gemm_attn<<<gemmGrid, 256>>>(bufA, W2, as2, ad2, bufB, aS, aD);
    k_aggregate<<<warpBlocks, 256>>>(rowptrB, csrcB, bufB, aS, aD, bb2, exB, bufA);
    k_gemm_attn<<<gemmGrid, 256>>>(bufA, W3, as3, ad3, bufB, aS, aD);
    k_aggregate<<<warpBlocks, 256>>>(rowptrB, csrcB, bufB, aS, aD, bb3, exB, bufA);

    k_final<<<N / FB, 256>>>(bufA, Wg, bg, Wf, bf, (float*)d_out);
}

// round 7
// speedup vs baseline: 5.3689x; 1.0789x over previous
#include <cuda_runtime.h>
#include <math.h>
#include <stdint.h>

// ---------------- problem constants -----------------------------------------
#define NNODE 19200
#define NEDGE 230400
#define NGRAPH 128
#define LATENT 256
#define FEAT 64
#define HEADS 4
#define POS 180
#define DMODEL 256       // HEADS * FEAT
#define ETOT (NEDGE + NNODE)
#define NBLK 75          // NNODE / 256
#define EBLK 900         // NEDGE / 256
#define WBLK 2400        // NNODE / 8 (8 warps per block)

// ---------------- static device scratch --------------------------------------
__device__ __align__(16) float g_bufA[NNODE * DMODEL];
__device__ __align__(16) float g_bufB[NNODE * DMODEL];
__device__ __align__(16) float g_as[NNODE * HEADS];
__device__ __align__(16) float g_ad[NNODE * HEADS];
__device__ __align__(16) float g_ex[ETOT * HEADS];
__device__ __align__(16) float g_pg[NGRAPH * DMODEL];
__device__ int g_starts[NGRAPH];
__device__ int g_deg[NNODE];
__device__ int g_rowptr[NNODE + 1];
__device__ int g_cursor[NNODE];
__device__ int g_csrc[ETOT];

// ---------------- fused prologue: x0pg | prep (deg init) -----------------------
// NOTE: hist must NOT be fused here — deg init and atomicAdd would race within
// one grid (caused the R6 failure).
__global__ void k_pro(const float* __restrict__ z, const float* __restrict__ W0,
                      const float* __restrict__ b0, const float* __restrict__ W1,
                      float* __restrict__ pg, const int* __restrict__ batch,
                      int* __restrict__ starts, int* __restrict__ deg) {
    int b = blockIdx.x;
    int t = threadIdx.x;
    if (b < NGRAPH) {
        __shared__ float xs[FEAT];
        if (t < FEAT) {
            float acc = b0[t];
            const float* zr = z + b * LATENT;
            #pragma unroll 4
            for (int k = 0; k < LATENT; k++) acc += zr[k] * W0[k * FEAT + t];
            xs[t] = acc > 0.0f ? acc : 0.0f;
        }
        __syncthreads();
        float a = 0.0f;
        #pragma unroll
        for (int k = 0; k < FEAT; k++) a += xs[k] * W1[k * DMODEL + t];
        pg[b * DMODEL + t] = a;
    } else {
        int i = (b - NGRAPH) * 256 + t;
        int bb = batch[i];
        if (i == 0 || batch[i - 1] != bb) starts[bb] = i;
        deg[i] = 1;                           // self loop slot
    }
}

__global__ void k_hist(const int* __restrict__ dst, int* __restrict__ deg) {
    int e = blockIdx.x * blockDim.x + threadIdx.x;
    atomicAdd(&deg[dst[e]], 1);
}

// ---------------- CSR: fused prefix + local scan + self-loop fill --------------
__global__ void k_fill2(const int* __restrict__ deg, int* __restrict__ rowptr,
                        int* __restrict__ cursor, int* __restrict__ csrc) {
    __shared__ int red[256];
    __shared__ int s[256];
    int t = threadIdx.x;
    int b = blockIdx.x;
    int lim = b * 256;
    int sum = 0;
    for (int i = t; i < lim; i += 256) sum += deg[i];
    red[t] = sum;
    __syncthreads();
    for (int off = 128; off > 0; off >>= 1) {
        if (t < off) red[t] += red[t + off];
        __syncthreads();
    }
    int node = lim + t;
    int d = deg[node];
    s[t] = d;
    __syncthreads();
    for (int off = 1; off < 256; off <<= 1) {
        int u = (t >= off) ? s[t - off] : 0;
        __syncthreads();
        s[t] += u;
        __syncthreads();
    }
    int r = red[0] + s[t] - d;                // exclusive prefix
    rowptr[node] = r;
    csrc[r] = node;                           // self loop first
    cursor[node] = r + 1;
    if (node == NNODE - 1) rowptr[NNODE] = red[0] + s[t];
}

// ---------------- fused: h1+attn | CSR scatter ----------------------------------
__global__ void k_mid(const float* __restrict__ pg, const float* __restrict__ W1,
                      const int* __restrict__ batch, const int* __restrict__ starts,
                      const float* __restrict__ attS, const float* __restrict__ attD,
                      float* __restrict__ H, float* __restrict__ aS,
                      float* __restrict__ aD,
                      const int* __restrict__ src, const int* __restrict__ dst,
                      int* __restrict__ cursor, int* __restrict__ csrc) {
    int b = blockIdx.x;
    int tid = threadIdx.x;
    if (b >= WBLK) {
        int e = (b - WBLK) * 256 + tid;
        int p = atomicAdd(&cursor[dst[e]], 1);
        csrc[p] = src[e];
        return;
    }
    __shared__ float sS[DMODEL], sD[DMODEL];
    if (tid < DMODEL) { sS[tid] = attS[tid]; sD[tid] = attD[tid]; }
    __syncthreads();
    int node = b * 8 + (tid >> 5);
    int lane = tid & 31;
    int g = batch[node];
    int order = node - starts[g];
    int c0 = lane * 8;
    const float4* pgr = (const float4*)(pg + g * DMODEL + c0);
    const float4* w1r = (const float4*)(W1 + (FEAT + order) * DMODEL + c0);
    float4 p0 = pgr[0], p1 = pgr[1];
    float4 w0 = w1r[0], w1v = w1r[1];
    float h[8];
    h[0] = p0.x + w0.x; h[1] = p0.y + w0.y; h[2] = p0.z + w0.z; h[3] = p0.w + w0.w;
    h[4] = p1.x + w1v.x; h[5] = p1.y + w1v.y; h[6] = p1.z + w1v.z; h[7] = p1.w + w1v.w;
    float* hr = H + node * DMODEL + c0;
    *(float4*)hr       = make_float4(h[0], h[1], h[2], h[3]);
    *(float4*)(hr + 4) = make_float4(h[4], h[5], h[6], h[7]);
    float pS = 0.0f, pD = 0.0f;
    #pragma unroll
    for (int j = 0; j < 8; j++) { pS += h[j] * sS[c0 + j]; pD += h[j] * sD[c0 + j]; }
    pS += __shfl_xor_sync(0xffffffffu, pS, 1);
    pS += __shfl_xor_sync(0xffffffffu, pS, 2);
    pS += __shfl_xor_sync(0xffffffffu, pS, 4);
    pD += __shfl_xor_sync(0xffffffffu, pD, 1);
    pD += __shfl_xor_sync(0xffffffffu, pD, 2);
    pD += __shfl_xor_sync(0xffffffffu, pD, 4);
    if ((lane & 7) == 0) {
        int hd = lane >> 3;
        aS[node * 4 + hd] = pS;
        aD[node * 4 + hd] = pD;
    }
}

// ---------------- tf32 tensor-core GEMM + fused attention logits ---------------
#define SMS 136
__device__ __forceinline__ uint32_t f2tf32(float v) {
    uint32_t r;
    asm("cvt.rna.tf32.f32 %0, %1;" : "=r"(r) : "f"(v));
    return r;
}
__device__ __forceinline__ void mma_tf32(float* c, uint32_t a0, uint32_t a1,
                                         uint32_t a2, uint32_t a3,
                                         uint32_t b0, uint32_t b1) {
    asm volatile(
        "mma.sync.aligned.m16n8k8.row.col.f32.tf32.tf32.f32 "
        "{%0,%1,%2,%3}, {%4,%5,%6,%7}, {%8,%9}, {%0,%1,%2,%3};"
        : "+f"(c[0]), "+f"(c[1]), "+f"(c[2]), "+f"(c[3])
        : "r"(a0), "r"(a1), "r"(a2), "r"(a3), "r"(b0), "r"(b1));
}

__global__ void __launch_bounds__(256, 1)
k_gemm_attn(const float* __restrict__ X, const float* __restrict__ W,
            const float* __restrict__ attS, const float* __restrict__ attD,
            float* __restrict__ C, float* __restrict__ aS, float* __restrict__ aD) {
    __shared__ uint32_t As[32][SMS];
    __shared__ uint32_t Bs[32][SMS];
    __shared__ float sS[128], sD[128];
    __shared__ float sPS[128][2], sPD[128][2];

    int tid = threadIdx.x;
    int lane = tid & 31;
    int w = tid >> 5;
    int wm = w & 1, wn = w >> 1;
    int r0 = blockIdx.x * 128;
    int c0 = blockIdx.y * 128;

    if (tid < 128) { sS[tid] = attS[c0 + tid]; sD[tid] = attD[c0 + tid]; }
    {
        int rr = tid >> 1, hh = tid & 1;
        sPS[rr][hh] = 0.0f;
        sPD[rr][hh] = 0.0f;
    }

    float acc[4][4][4];
    #pragma unroll
    for (int i = 0; i < 4; i++)
        #pragma unroll
        for (int j = 0; j < 4; j++)
            #pragma unroll
            for (int q = 0; q < 4; q++) acc[i][j][q] = 0.0f;

    int am = tid >> 1;
    int ak = (tid & 1) * 16;
    int bkr = tid >> 3;
    int bn = (tid & 7) * 16;

    #pragma unroll 1
    for (int kc = 0; kc < DMODEL; kc += 32) {
        const float4* ap = (const float4*)(X + (r0 + am) * DMODEL + kc + ak);
        #pragma unroll
        for (int q = 0; q < 4; q++) {
            float4 v = ap[q];
            As[ak + q * 4 + 0][am] = f2tf32(v.x);
            As[ak + q * 4 + 1][am] = f2tf32(v.y);
            As[ak + q * 4 + 2][am] = f2tf32(v.z);
            As[ak + q * 4 + 3][am] = f2tf32(v.w);
        }
        const float4* bp = (const float4*)(W + (kc + bkr) * DMODEL + c0 + bn);
        #pragma unroll
        for (int q = 0; q < 4; q++) {
            float4 v = bp[q];
            uint4 u;
            u.x = f2tf32(v.x); u.y = f2tf32(v.y);
            u.z = f2tf32(v.z); u.w = f2tf32(v.w);
            *(uint4*)&Bs[bkr][bn + q * 4] = u;
        }
        __syncthreads();

        #pragma unroll
        for (int kk = 0; kk < 4; kk++) {
            int kb = kk * 8;
            int klo = kb + (lane & 3), khi = klo + 4;
            uint32_t afr[4][4], bfr[4][2];
            #pragma unroll
            for (int mt = 0; mt < 4; mt++) {
                int m = wm * 64 + mt * 16 + (lane >> 2);
                afr[mt][0] = As[klo][m];
                afr[mt][1] = As[klo][m + 8];
                afr[mt][2] = As[khi][m];
                afr[mt][3] = As[khi][m + 8];
            }
            #pragma unroll
            for (int nt = 0; nt < 4; nt++) {
                int n = wn * 32 + nt * 8 + (lane >> 2);
                bfr[nt][0] = Bs[klo][n];
                bfr[nt][1] = Bs[khi][n];
            }
            #pragma unroll
            for (int mt = 0; mt < 4; mt++)
                #pragma unroll
                for (int nt = 0; nt < 4; nt++)
                    mma_tf32(acc[mt][nt], afr[mt][0], afr[mt][1], afr[mt][2],
                             afr[mt][3], bfr[nt][0], bfr[nt][1]);
        }
        __syncthreads();
    }

    int hb = wn >> 1;
    #pragma unroll
    for (int mt = 0; mt < 4; mt++) {
        int rowA = wm * 64 + mt * 16 + (lane >> 2);
        int rowB = rowA + 8;
        float pSa = 0.0f, pDa = 0.0f, pSb = 0.0f, pDb = 0.0f;
        #pragma unroll
        for (int nt = 0; nt < 4; nt++) {
            int lc = wn * 32 + nt * 8 + 2 * (lane & 3);
            float s0 = sS[lc], s1 = sS[lc + 1];
            float d0 = sD[lc], d1 = sD[lc + 1];
            float* a = acc[mt][nt];
            pSa += a[0] * s0 + a[1] * s1;
            pDa += a[0] * d0 + a[1] * d1;
            pSb += a[2] * s0 + a[3] * s1;
            pDb += a[2] * d0 + a[3] * d1;
            float* cpA = C + (r0 + rowA) * DMODEL + c0 + lc;
            float* cpB = C + (r0 + rowB) * DMODEL + c0 + lc;
            *(float2*)cpA = make_float2(a[0], a[1]);
            *(float2*)cpB = make_float2(a[2], a[3]);
        }
        pSa += __shfl_xor_sync(0xffffffffu, pSa, 1);
        pSa += __shfl_xor_sync(0xffffffffu, pSa, 2);
        pDa += __shfl_xor_sync(0xffffffffu, pDa, 1);
        pDa += __shfl_xor_sync(0xffffffffu, pDa, 2);
        pSb += __shfl_xor_sync(0xffffffffu, pSb, 1);
        pSb += __shfl_xor_sync(0xffffffffu, pSb, 2);
        pDb += __shfl_xor_sync(0xffffffffu, pDb, 1);
        pDb += __shfl_xor_sync(0xffffffffu, pDb, 2);
        if ((lane & 3) == 0) {
            atomicAdd(&sPS[rowA][hb], pSa);
            atomicAdd(&sPD[rowA][hb], pDa);
            atomicAdd(&sPS[rowB][hb], pSb);
            atomicAdd(&sPD[rowB][hb], pDb);
        }
    }
    __syncthreads();
    {
        int rr = tid >> 1, hh = tid & 1;
        int node = r0 + rr;
        int head = blockIdx.y * 2 + hh;
        aS[node * 4 + head] = sPS[rr][hh];
        aD[node * 4 + head] = sPD[rr][hh];
    }
}

// ---------------- segment softmax + weighted aggregate (device body) ----------
__device__ __forceinline__ float lrelu(float v) { return v > 0.0f ? v : 0.2f * v; }

__device__ __forceinline__ void aggregate_node(
    int node, int lane, const int* __restrict__ rowptr, const int* __restrict__ csrc,
    const float* __restrict__ H, const float* __restrict__ aS,
    const float* __restrict__ aD, const float* __restrict__ bias,
    float* __restrict__ ex, float r[8]) {
    int rs = rowptr[node], re = rowptr[node + 1];
    float4 ad = *(const float4*)(aD + node * 4);

    float m0 = -1e30f, m1 = -1e30f, m2 = -1e30f, m3 = -1e30f;
    for (int e = rs + lane; e < re; e += 32) {
        int s = csrc[e];
        float4 as = *(const float4*)(aS + s * 4);
        m0 = fmaxf(m0, lrelu(as.x + ad.x));
        m1 = fmaxf(m1, lrelu(as.y + ad.y));
        m2 = fmaxf(m2, lrelu(as.z + ad.z));
        m3 = fmaxf(m3, lrelu(as.w + ad.w));
    }
    #pragma unroll
    for (int o = 16; o > 0; o >>= 1) {
        m0 = fmaxf(m0, __shfl_xor_sync(0xffffffffu, m0, o));
        m1 = fmaxf(m1, __shfl_xor_sync(0xffffffffu, m1, o));
        m2 = fmaxf(m2, __shfl_xor_sync(0xffffffffu, m2, o));
        m3 = fmaxf(m3, __shfl_xor_sync(0xffffffffu, m3, o));
    }
    float s0 = 0, s1 = 0, s2 = 0, s3 = 0;
    for (int e = rs + lane; e < re; e += 32) {
        int s = csrc[e];
        float4 as = *(const float4*)(aS + s * 4);
        float x0 = expf(lrelu(as.x + ad.x) - m0);
        float x1 = expf(lrelu(as.y + ad.y) - m1);
        float x2 = expf(lrelu(as.z + ad.z) - m2);
        float x3 = expf(lrelu(as.w + ad.w) - m3);
        *(float4*)(ex + e * 4) = make_float4(x0, x1, x2, x3);
        s0 += x0; s1 += x1; s2 += x2; s3 += x3;
    }
    #pragma unroll
    for (int o = 16; o > 0; o >>= 1) {
        s0 += __shfl_xor_sync(0xffffffffu, s0, o);
        s1 += __shfl_xor_sync(0xffffffffu, s1, o);
        s2 += __shfl_xor_sync(0xffffffffu, s2, o);
        s3 += __shfl_xor_sync(0xffffffffu, s3, o);
    }
    int head = lane >> 3;
    float sh = head == 0 ? s0 : head == 1 ? s1 : head == 2 ? s2 : s3;
    float inv = 1.0f / (sh + 1e-16f);

    float acc[8] = {};
    int sNext = csrc[rs];
    for (int e = rs; e < re; e++) {
        int s = sNext;
        if (e + 1 < re) sNext = csrc[e + 1];
        float alpha = __ldg(ex + e * 4 + head) * inv;
        const float4* hp = (const float4*)(H + s * DMODEL + lane * 8);
        float4 h0 = hp[0], h1 = hp[1];
        acc[0] += alpha * h0.x; acc[1] += alpha * h0.y;
        acc[2] += alpha * h0.z; acc[3] += alpha * h0.w;
        acc[4] += alpha * h1.x; acc[5] += alpha * h1.y;
        acc[6] += alpha * h1.z; acc[7] += alpha * h1.w;
    }
    const float4* bp = (const float4*)(bias + lane * 8);
    float4 b0 = bp[0], b1 = bp[1];
    r[0] = acc[0] + b0.x; r[1] = acc[1] + b0.y; r[2] = acc[2] + b0.z; r[3] = acc[3] + b0.w;
    r[4] = acc[4] + b1.x; r[5] = acc[5] + b1.y; r[6] = acc[6] + b1.z; r[7] = acc[7] + b1.w;
    #pragma unroll
    for (int i = 0; i < 8; i++) r[i] = r[i] > 0.0f ? r[i] : 0.0f;
}

__global__ void k_aggregate(const int* __restrict__ rowptr, const int* __restrict__ csrc,
                            const float* __restrict__ H, const float* __restrict__ aS,
                            const float* __restrict__ aD, const float* __restrict__ bias,
                            float* __restrict__ ex, float* __restrict__ out) {
    int node = (blockIdx.x * blockDim.x + threadIdx.x) >> 5;
    int lane = threadIdx.x & 31;
    if (node >= NNODE) return;
    float r[8];
    aggregate_node(node, lane, rowptr, csrc, H, aS, aD, bias, ex, r);
    float* op = out + node * DMODEL + lane * 8;
    *(float4*)op       = make_float4(r[0], r[1], r[2], r[3]);
    *(float4*)(op + 4) = make_float4(r[4], r[5], r[6], r[7]);
}

// ---------------- fused: layer-3 aggregate + dec_geo + fc_geo ------------------
__global__ void __launch_bounds__(256)
k_agg_final(const int* __restrict__ rowptr, const int* __restrict__ csrc,
            const float* __restrict__ H, const float* __restrict__ aS,
            const float* __restrict__ aD, const float* __restrict__ bias,
            float* __restrict__ ex,
            const float* __restrict__ Wg, const float* __restrict__ bg,
            const float* __restrict__ Wf, const float* __restrict__ bf,
            float* __restrict__ out) {
    __shared__ float sWg[128][FEAT];          // 32 KB (one 128-row K chunk)
    __shared__ float sx[8][DMODEL];           // 8 KB node features
    __shared__ float sWf[FEAT * 5];           // 1.25 KB

    int tid = threadIdx.x;
    int w = tid >> 5;
    int lane = tid & 31;
    int node = blockIdx.x * 8 + w;

    for (int i = tid; i < FEAT * 5; i += 256) sWf[i] = Wf[i];

    float r[8];
    aggregate_node(node, lane, rowptr, csrc, H, aS, aD, bias, ex, r);
    float* sxp = &sx[w][lane * 8];
    *(float4*)sxp       = make_float4(r[0], r[1], r[2], r[3]);
    *(float4*)(sxp + 4) = make_float4(r[4], r[5], r[6], r[7]);
    __syncthreads();

    // y[j] for j = lane and j = lane+32
    float y0 = bg[lane], y1 = bg[lane + 32];
    #pragma unroll 1
    for (int kc = 0; kc < DMODEL; kc += 128) {
        #pragma unroll
        for (int t2 = 0; t2 < 8; t2++) {
            int idx = (tid + t2 * 256) * 4;
            *(float4*)&sWg[idx >> 6][idx & 63] =
                *(const float4*)(Wg + kc * FEAT + idx);
        }
        __syncthreads();
        #pragma unroll 4
        for (int k = 0; k < 128; k++) {
            float xv = sx[w][kc + k];
            y0 += xv * sWg[k][lane];
            y1 += xv * sWg[k][lane + 32];
        }
        __syncthreads();
    }
    y0 = y0 > 0.0f ? y0 : 0.0f;
    y1 = y1 > 0.0f ? y1 : 0.0f;

    float p[5];
    #pragma unroll
    for (int c = 0; c < 5; c++)
        p[c] = y0 * sWf[lane * 5 + c] + y1 * sWf[(lane + 32) * 5 + c];
    #pragma unroll
    for (int o = 16; o > 0; o >>= 1) {
        #pragma unroll
        for (int c = 0; c < 5; c++)
            p[c] += __shfl_xor_sync(0xffffffffu, p[c], o);
    }
    if (lane == 0) {
        #pragma unroll
        for (int c = 0; c < 5; c++)
            out[node * 5 + c] = p[c] + bf[c];
    }
}

// ---------------- host orchestration ------------------------------------------
extern "C" void kernel_launch(void* const* d_in, const int* in_sizes, int n_in,
                              void* d_out, int out_size) {
    const float* z     = (const float*)d_in[0];
    const int*   ei    = (const int*)d_in[1];
    const int*   batch = (const int*)d_in[2];
    int base = (in_sizes[3] == 1) ? 4 : 3;
    const float* W0  = (const float*)d_in[base + 0];
    const float* b0  = (const float*)d_in[base + 1];
    const float* W1  = (const float*)d_in[base + 2];
    const float* as1 = (const float*)d_in[base + 3];
    const float* ad1 = (const float*)d_in[base + 4];
    const float* bb1 = (const float*)d_in[base + 5];
    const float* W2  = (const float*)d_in[base + 6];
    const float* as2 = (const float*)d_in[base + 7];
    const float* ad2 = (const float*)d_in[base + 8];
    const float* bb2 = (const float*)d_in[base + 9];
    const float* W3  = (const float*)d_in[base + 10];
    const float* as3 = (const float*)d_in[base + 11];
    const float* ad3 = (const float*)d_in[base + 12];
    const float* bb3 = (const float*)d_in[base + 13];
    const float* Wg  = (const float*)d_in[base + 14];
    const float* bg  = (const float*)d_in[base + 15];
    const float* Wf  = (const float*)d_in[base + 16];
    const float* bf  = (const float*)d_in[base + 17];

    const int* srcArr = ei;
    const int* dstArr = ei + NEDGE;

    float *bufA, *bufB, *aS, *aD, *exB, *pgB;
    int *startsB, *degB, *rowptrB, *cursorB, *csrcB;
    cudaGetSymbolAddress((void**)&bufA, g_bufA);
    cudaGetSymbolAddress((void**)&bufB, g_bufB);
    cudaGetSymbolAddress((void**)&aS, g_as);
    cudaGetSymbolAddress((void**)&aD, g_ad);
    cudaGetSymbolAddress((void**)&exB, g_ex);
    cudaGetSymbolAddress((void**)&pgB, g_pg);
    cudaGetSymbolAddress((void**)&startsB, g_starts);
    cudaGetSymbolAddress((void**)&degB, g_deg);
    cudaGetSymbolAddress((void**)&rowptrB, g_rowptr);
    cudaGetSymbolAddress((void**)&cursorB, g_cursor);
    cudaGetSymbolAddress((void**)&csrcB, g_csrc);

    dim3 gemmGrid(NNODE / 128, 2);

    // 1: prologue (x0pg | starts + deg init)
    k_pro<<<NGRAPH + NBLK, 256>>>(z, W0, b0, W1, pgB, batch, startsB, degB);
    // 2: degree histogram (must follow deg init across a launch boundary)
    k_hist<<<EBLK, 256>>>(dstArr, degB);
    // 3: CSR rowptr + self-loop fill
    k_fill2<<<NBLK, 256>>>(degB, rowptrB, cursorB, csrcB);
    // 4: h1+attn | scatter
    k_mid<<<WBLK + EBLK, 256>>>(pgB, W1, batch, startsB, as1, ad1, bufB, aS, aD,
                                srcArr, dstArr, cursorB, csrcB);
    // 5: aggregate layer 1
    k_aggregate<<<WBLK, 256>>>(rowptrB, csrcB, bufB, aS, aD, bb1, exB, bufA);
    // 6-7: layer 2
    k_gemm_attn<<<gemmGrid, 256>>>(bufA, W2, as2, ad2, bufB, aS, aD);
    k_aggregate<<<WBLK, 256>>>(rowptrB, csrcB, bufB, aS, aD, bb2, exB, bufA);
    // 8: layer 3 GEMM
    k_gemm_attn<<<gemmGrid, 256>>>(bufA, W3, as3, ad3, bufB, aS, aD);
    // 9: layer 3 aggregate fused with dec_geo + fc_geo
    k_agg_final<<<WBLK, 256>>>(rowptrB, csrcB, bufB, aS, aD, bb3, exB,
                               Wg, bg, Wf, bf, (float*)d_out);
}

// round 8
// speedup vs baseline: 5.4208x; 1.0097x over previous
#include <cuda_runtime.h>
#include <math.h>
#include <stdint.h>

// ---------------- problem constants -----------------------------------------
#define NNODE 19200
#define NEDGE 230400
#define NGRAPH 128
#define LATENT 256
#define FEAT 64
#define HEADS 4
#define POS 180
#define DMODEL 256       // HEADS * FEAT
#define ETOT (NEDGE + NNODE)
#define NBLK 75          // NNODE / 256
#define EBLK 900         // NEDGE / 256
#define WBLK 2400        // NNODE / 8 (8 warps per block)

// ---------------- static device scratch --------------------------------------
__device__ __align__(16) float g_bufA[NNODE * DMODEL];
__device__ __align__(16) float g_bufB[NNODE * DMODEL];
__device__ __align__(16) float g_as[NNODE * HEADS];
__device__ __align__(16) float g_ad[NNODE * HEADS];
__device__ __align__(16) float g_ex[ETOT * HEADS];
__device__ __align__(16) float g_pg[NGRAPH * DMODEL];
__device__ int g_starts[NGRAPH];
__device__ int g_deg[NNODE];      // zero-initialized at load; re-zeroed each replay in k_mid
__device__ int g_rowptr[NNODE + 1];
__device__ int g_cursor[NNODE];
__device__ int g_csrc[ETOT];

// ---------------- fused prologue: x0pg | starts | hist -------------------------
// deg is guaranteed zero on entry (module-load zero-init on first call,
// re-zeroed by k_mid on every subsequent call), so the histogram atomics can
// run concurrently with the other block ranges — no init/atomic race.
__global__ void k_pro(const float* __restrict__ z, const float* __restrict__ W0,
                      const float* __restrict__ b0, const float* __restrict__ W1,
                      float* __restrict__ pg, const int* __restrict__ batch,
                      int* __restrict__ starts, int* __restrict__ deg,
                      const int* __restrict__ dst) {
    int b = blockIdx.x;
    int t = threadIdx.x;
    if (b < NGRAPH) {
        __shared__ float xs[FEAT];
        if (t < FEAT) {
            float acc = b0[t];
            const float* zr = z + b * LATENT;
            #pragma unroll 4
            for (int k = 0; k < LATENT; k++) acc += zr[k] * W0[k * FEAT + t];
            xs[t] = acc > 0.0f ? acc : 0.0f;
        }
        __syncthreads();
        float a = 0.0f;
        #pragma unroll
        for (int k = 0; k < FEAT; k++) a += xs[k] * W1[k * DMODEL + t];
        pg[b * DMODEL + t] = a;
    } else if (b < NGRAPH + NBLK) {
        int i = (b - NGRAPH) * 256 + t;
        int bb = batch[i];
        if (i == 0 || batch[i - 1] != bb) starts[bb] = i;
    } else {
        int e = (b - NGRAPH - NBLK) * 256 + t;
        atomicAdd(&deg[dst[e]], 1);
    }
}

// ---------------- CSR: prefix + local scan + self-loop fill --------------------
__global__ void k_fill2(const int* __restrict__ deg, int* __restrict__ rowptr,
                        int* __restrict__ cursor, int* __restrict__ csrc) {
    __shared__ int red[256];
    __shared__ int s[256];
    int t = threadIdx.x;
    int b = blockIdx.x;
    int lim = b * 256;
    int sum = 0;
    for (int i = t; i < lim; i += 256) sum += deg[i] + 1;   // +1 self loop
    red[t] = sum;
    __syncthreads();
    for (int off = 128; off > 0; off >>= 1) {
        if (t < off) red[t] += red[t + off];
        __syncthreads();
    }
    int node = lim + t;
    int d = deg[node] + 1;                    // +1 self loop
    s[t] = d;
    __syncthreads();
    for (int off = 1; off < 256; off <<= 1) {
        int u = (t >= off) ? s[t - off] : 0;
        __syncthreads();
        s[t] += u;
        __syncthreads();
    }
    int r = red[0] + s[t] - d;                // exclusive prefix
    rowptr[node] = r;
    csrc[r] = node;                           // self loop first
    cursor[node] = r + 1;
    if (node == NNODE - 1) rowptr[NNODE] = red[0] + s[t];
}

// ---------------- fused: h1+attn | CSR scatter | deg re-zero --------------------
__global__ void k_mid(const float* __restrict__ pg, const float* __restrict__ W1,
                      const int* __restrict__ batch, const int* __restrict__ starts,
                      const float* __restrict__ attS, const float* __restrict__ attD,
                      float* __restrict__ H, float* __restrict__ aS,
                      float* __restrict__ aD,
                      const int* __restrict__ src, const int* __restrict__ dst,
                      int* __restrict__ cursor, int* __restrict__ csrc,
                      int* __restrict__ deg) {
    int b = blockIdx.x;
    int tid = threadIdx.x;
    if (b >= WBLK + EBLK) {
        // re-zero deg for the next replay (deg was consumed by k_fill2 last launch)
        deg[(b - WBLK - EBLK) * 256 + tid] = 0;
        return;
    }
    if (b >= WBLK) {
        int e = (b - WBLK) * 256 + tid;
        int p = atomicAdd(&cursor[dst[e]], 1);
        csrc[p] = src[e];
        return;
    }
    __shared__ float sS[DMODEL], sD[DMODEL];
    if (tid < DMODEL) { sS[tid] = attS[tid]; sD[tid] = attD[tid]; }
    __syncthreads();
    int node = b * 8 + (tid >> 5);
    int lane = tid & 31;
    int g = batch[node];
    int order = node - starts[g];
    int c0 = lane * 8;
    const float4* pgr = (const float4*)(pg + g * DMODEL + c0);
    const float4* w1r = (const float4*)(W1 + (FEAT + order) * DMODEL + c0);
    float4 p0 = pgr[0], p1 = pgr[1];
    float4 w0 = w1r[0], w1v = w1r[1];
    float h[8];
    h[0] = p0.x + w0.x; h[1] = p0.y + w0.y; h[2] = p0.z + w0.z; h[3] = p0.w + w0.w;
    h[4] = p1.x + w1v.x; h[5] = p1.y + w1v.y; h[6] = p1.z + w1v.z; h[7] = p1.w + w1v.w;
    float* hr = H + node * DMODEL + c0;
    *(float4*)hr       = make_float4(h[0], h[1], h[2], h[3]);
    *(float4*)(hr + 4) = make_float4(h[4], h[5], h[6], h[7]);
    float pS = 0.0f, pD = 0.0f;
    #pragma unroll
    for (int j = 0; j < 8; j++) { pS += h[j] * sS[c0 + j]; pD += h[j] * sD[c0 + j]; }
    pS += __shfl_xor_sync(0xffffffffu, pS, 1);
    pS += __shfl_xor_sync(0xffffffffu, pS, 2);
    pS += __shfl_xor_sync(0xffffffffu, pS, 4);
    pD += __shfl_xor_sync(0xffffffffu, pD, 1);
    pD += __shfl_xor_sync(0xffffffffu, pD, 2);
    pD += __shfl_xor_sync(0xffffffffu, pD, 4);
    if ((lane & 7) == 0) {
        int hd = lane >> 3;
        aS[node * 4 + hd] = pS;
        aD[node * 4 + hd] = pD;
    }
}

// ---------------- tf32 tensor-core GEMM + fused attention logits ---------------
#define SMS 136
__device__ __forceinline__ uint32_t f2tf32(float v) {
    uint32_t r;
    asm("cvt.rna.tf32.f32 %0, %1;" : "=r"(r) : "f"(v));
    return r;
}
__device__ __forceinline__ void mma_tf32(float* c, uint32_t a0, uint32_t a1,
                                         uint32_t a2, uint32_t a3,
                                         uint32_t b0, uint32_t b1) {
    asm volatile(
        "mma.sync.aligned.m16n8k8.row.col.f32.tf32.tf32.f32 "
        "{%0,%1,%2,%3}, {%4,%5,%6,%7}, {%8,%9}, {%0,%1,%2,%3};"
        : "+f"(c[0]), "+f"(c[1]), "+f"(c[2]), "+f"(c[3])
        : "r"(a0), "r"(a1), "r"(a2), "r"(a3), "r"(b0), "r"(b1));
}

__global__ void __launch_bounds__(256, 1)
k_gemm_attn(const float* __restrict__ X, const float* __restrict__ W,
            const float* __restrict__ attS, const float* __restrict__ attD,
            float* __restrict__ C, float* __restrict__ aS, float* __restrict__ aD) {
    __shared__ uint32_t As[32][SMS];
    __shared__ uint32_t Bs[32][SMS];
    __shared__ float sS[128], sD[128];
    __shared__ float sPS[128][2], sPD[128][2];

    int tid = threadIdx.x;
    int lane = tid & 31;
    int w = tid >> 5;
    int wm = w & 1, wn = w >> 1;
    int r0 = blockIdx.x * 128;
    int c0 = blockIdx.y * 128;

    if (tid < 128) { sS[tid] = attS[c0 + tid]; sD[tid] = attD[c0 + tid]; }
    {
        int rr = tid >> 1, hh = tid & 1;
        sPS[rr][hh] = 0.0f;
        sPD[rr][hh] = 0.0f;
    }

    float acc[4][4][4];
    #pragma unroll
    for (int i = 0; i < 4; i++)
        #pragma unroll
        for (int j = 0; j < 4; j++)
            #pragma unroll
            for (int q = 0; q < 4; q++) acc[i][j][q] = 0.0f;

    int am = tid >> 1;
    int ak = (tid & 1) * 16;
    int bkr = tid >> 3;
    int bn = (tid & 7) * 16;

    #pragma unroll 1
    for (int kc = 0; kc < DMODEL; kc += 32) {
        const float4* ap = (const float4*)(X + (r0 + am) * DMODEL + kc + ak);
        #pragma unroll
        for (int q = 0; q < 4; q++) {
            float4 v = ap[q];
            As[ak + q * 4 + 0][am] = f2tf32(v.x);
            As[ak + q * 4 + 1][am] = f2tf32(v.y);
            As[ak + q * 4 + 2][am] = f2tf32(v.z);
            As[ak + q * 4 + 3][am] = f2tf32(v.w);
        }
        const float4* bp = (const float4*)(W + (kc + bkr) * DMODEL + c0 + bn);
        #pragma unroll
        for (int q = 0; q < 4; q++) {
            float4 v = bp[q];
            uint4 u;
            u.x = f2tf32(v.x); u.y = f2tf32(v.y);
            u.z = f2tf32(v.z); u.w = f2tf32(v.w);
            *(uint4*)&Bs[bkr][bn + q * 4] = u;
        }
        __syncthreads();

        #pragma unroll
        for (int kk = 0; kk < 4; kk++) {
            int kb = kk * 8;
            int klo = kb + (lane & 3), khi = klo + 4;
            uint32_t afr[4][4], bfr[4][2];
            #pragma unroll
            for (int mt = 0; mt < 4; mt++) {
                int m = wm * 64 + mt * 16 + (lane >> 2);
                afr[mt][0] = As[klo][m];
                afr[mt][1] = As[klo][m + 8];
                afr[mt][2] = As[khi][m];
                afr[mt][3] = As[khi][m + 8];
            }
            #pragma unroll
            for (int nt = 0; nt < 4; nt++) {
                int n = wn * 32 + nt * 8 + (lane >> 2);
                bfr[nt][0] = Bs[klo][n];
                bfr[nt][1] = Bs[khi][n];
            }
            #pragma unroll
            for (int mt = 0; mt < 4; mt++)
                #pragma unroll
                for (int nt = 0; nt < 4; nt++)
                    mma_tf32(acc[mt][nt], afr[mt][0], afr[mt][1], afr[mt][2],
                             afr[mt][3], bfr[nt][0], bfr[nt][1]);
        }
        __syncthreads();
    }

    int hb = wn >> 1;
    #pragma unroll
    for (int mt = 0; mt < 4; mt++) {
        int rowA = wm * 64 + mt * 16 + (lane >> 2);
        int rowB = rowA + 8;
        float pSa = 0.0f, pDa = 0.0f, pSb = 0.0f, pDb = 0.0f;
        #pragma unroll
        for (int nt = 0; nt < 4; nt++) {
            int lc = wn * 32 + nt * 8 + 2 * (lane & 3);
            float s0 = sS[lc], s1 = sS[lc + 1];
            float d0 = sD[lc], d1 = sD[lc + 1];
            float* a = acc[mt][nt];
            pSa += a[0] * s0 + a[1] * s1;
            pDa += a[0] * d0 + a[1] * d1;
            pSb += a[2] * s0 + a[3] * s1;
            pDb += a[2] * d0 + a[3] * d1;
            float* cpA = C + (r0 + rowA) * DMODEL + c0 + lc;
            float* cpB = C + (r0 + rowB) * DMODEL + c0 + lc;
            *(float2*)cpA = make_float2(a[0], a[1]);
            *(float2*)cpB = make_float2(a[2], a[3]);
        }
        pSa += __shfl_xor_sync(0xffffffffu, pSa, 1);
        pSa += __shfl_xor_sync(0xffffffffu, pSa, 2);
        pDa += __shfl_xor_sync(0xffffffffu, pDa, 1);
        pDa += __shfl_xor_sync(0xffffffffu, pDa, 2);
        pSb += __shfl_xor_sync(0xffffffffu, pSb, 1);
        pSb += __shfl_xor_sync(0xffffffffu, pSb, 2);
        pDb += __shfl_xor_sync(0xffffffffu, pDb, 1);
        pDb += __shfl_xor_sync(0xffffffffu, pDb, 2);
        if ((lane & 3) == 0) {
            atomicAdd(&sPS[rowA][hb], pSa);
            atomicAdd(&sPD[rowA][hb], pDa);
            atomicAdd(&sPS[rowB][hb], pSb);
            atomicAdd(&sPD[rowB][hb], pDb);
        }
    }
    __syncthreads();
    {
        int rr = tid >> 1, hh = tid & 1;
        int node = r0 + rr;
        int head = blockIdx.y * 2 + hh;
        aS[node * 4 + head] = sPS[rr][hh];
        aD[node * 4 + head] = sPD[rr][hh];
    }
}

// ---------------- segment softmax + weighted aggregate (device body) ----------
__device__ __forceinline__ float lrelu(float v) { return v > 0.0f ? v : 0.2f * v; }

__device__ __forceinline__ void aggregate_node(
    int node, int lane, const int* __restrict__ rowptr, const int* __restrict__ csrc,
    const float* __restrict__ H, const float* __restrict__ aS,
    const float* __restrict__ aD, const float* __restrict__ bias,
    float* __restrict__ ex, float r[8]) {
    int rs = rowptr[node], re = rowptr[node + 1];
    float4 ad = *(const float4*)(aD + node * 4);

    // pass 1: compute logits once, store raw e to ex, track max
    float m0 = -1e30f, m1 = -1e30f, m2 = -1e30f, m3 = -1e30f;
    for (int e = rs + lane; e < re; e += 32) {
        int s = csrc[e];
        float4 as = *(const float4*)(aS + s * 4);
        float e0 = lrelu(as.x + ad.x);
        float e1 = lrelu(as.y + ad.y);
        float e2 = lrelu(as.z + ad.z);
        float e3 = lrelu(as.w + ad.w);
        *(float4*)(ex + e * 4) = make_float4(e0, e1, e2, e3);
        m0 = fmaxf(m0, e0); m1 = fmaxf(m1, e1);
        m2 = fmaxf(m2, e2); m3 = fmaxf(m3, e3);
    }
    #pragma unroll
    for (int o = 16; o > 0; o >>= 1) {
        m0 = fmaxf(m0, __shfl_xor_sync(0xffffffffu, m0, o));
        m1 = fmaxf(m1, __shfl_xor_sync(0xffffffffu, m1, o));
        m2 = fmaxf(m2, __shfl_xor_sync(0xffffffffu, m2, o));
        m3 = fmaxf(m3, __shfl_xor_sync(0xffffffffu, m3, o));
    }
    // pass 1b: re-read local ex (L1-hot, coalesced), exp, write back, sum
    float s0 = 0, s1 = 0, s2 = 0, s3 = 0;
    for (int e = rs + lane; e < re; e += 32) {
        float4 ev = *(const float4*)(ex + e * 4);
        float x0 = expf(ev.x - m0);
        float x1 = expf(ev.y - m1);
        float x2 = expf(ev.z - m2);
        float x3 = expf(ev.w - m3);
        *(float4*)(ex + e * 4) = make_float4(x0, x1, x2, x3);
        s0 += x0; s1 += x1; s2 += x2; s3 += x3;
    }
    #pragma unroll
    for (int o = 16; o > 0; o >>= 1) {
        s0 += __shfl_xor_sync(0xffffffffu, s0, o);
        s1 += __shfl_xor_sync(0xffffffffu, s1, o);
        s2 += __shfl_xor_sync(0xffffffffu, s2, o);
        s3 += __shfl_xor_sync(0xffffffffu, s3, o);
    }
    int head = lane >> 3;
    float sh = head == 0 ? s0 : head == 1 ? s1 : head == 2 ? s2 : s3;
    float inv = 1.0f / (sh + 1e-16f);

    float acc[8] = {};
    int sNext = csrc[rs];
    for (int e = rs; e < re; e++) {
        int s = sNext;
        if (e + 1 < re) sNext = csrc[e + 1];
        float alpha = __ldg(ex + e * 4 + head) * inv;
        const float4* hp = (const float4*)(H + s * DMODEL + lane * 8);
        float4 h0 = hp[0], h1 = hp[1];
        acc[0] += alpha * h0.x; acc[1] += alpha * h0.y;
        acc[2] += alpha * h0.z; acc[3] += alpha * h0.w;
        acc[4] += alpha * h1.x; acc[5] += alpha * h1.y;
        acc[6] += alpha * h1.z; acc[7] += alpha * h1.w;
    }
    const float4* bp = (const float4*)(bias + lane * 8);
    float4 b0 = bp[0], b1 = bp[1];
    r[0] = acc[0] + b0.x; r[1] = acc[1] + b0.y; r[2] = acc[2] + b0.z; r[3] = acc[3] + b0.w;
    r[4] = acc[4] + b1.x; r[5] = acc[5] + b1.y; r[6] = acc[6] + b1.z; r[7] = acc[7] + b1.w;
    #pragma unroll
    for (int i = 0; i < 8; i++) r[i] = r[i] > 0.0f ? r[i] : 0.0f;
}

__global__ void k_aggregate(const int* __restrict__ rowptr, const int* __restrict__ csrc,
                            const float* __restrict__ H, const float* __restrict__ aS,
                            const float* __restrict__ aD, const float* __restrict__ bias,
                            float* __restrict__ ex, float* __restrict__ out) {
    int node = (blockIdx.x * blockDim.x + threadIdx.x) >> 5;
    int lane = threadIdx.x & 31;
    if (node >= NNODE) return;
    float r[8];
    aggregate_node(node, lane, rowptr, csrc, H, aS, aD, bias, ex, r);
    float* op = out + node * DMODEL + lane * 8;
    *(float4*)op       = make_float4(r[0], r[1], r[2], r[3]);
    *(float4*)(op + 4) = make_float4(r[4], r[5], r[6], r[7]);
}

// ---------------- fused: layer-3 aggregate + dec_geo + fc_geo ------------------
__global__ void __launch_bounds__(256)
k_agg_final(const int* __restrict__ rowptr, const int* __restrict__ csrc,
            const float* __restrict__ H, const float* __restrict__ aS,
            const float* __restrict__ aD, const float* __restrict__ bias,
            float* __restrict__ ex,
            const float* __restrict__ Wg, const float* __restrict__ bg,
            const float* __restrict__ Wf, const float* __restrict__ bf,
            float* __restrict__ out) {
    __shared__ float sWg[128][FEAT];
    __shared__ float sx[8][DMODEL];
    __shared__ float sWf[FEAT * 5];

    int tid = threadIdx.x;
    int w = tid >> 5;
    int lane = tid & 31;
    int node = blockIdx.x * 8 + w;

    for (int i = tid; i < FEAT * 5; i += 256) sWf[i] = Wf[i];

    float r[8];
    aggregate_node(node, lane, rowptr, csrc, H, aS, aD, bias, ex, r);
    float* sxp = &sx[w][lane * 8];
    *(float4*)sxp       = make_float4(r[0], r[1], r[2], r[3]);
    *(float4*)(sxp + 4) = make_float4(r[4], r[5], r[6], r[7]);
    __syncthreads();

    float y0 = bg[lane], y1 = bg[lane + 32];
    #pragma unroll 1
    for (int kc = 0; kc < DMODEL; kc += 128) {
        #pragma unroll
        for (int t2 = 0; t2 < 8; t2++) {
            int idx = (tid + t2 * 256) * 4;
            *(float4*)&sWg[idx >> 6][idx & 63] =
                *(const float4*)(Wg + kc * FEAT + idx);
        }
        __syncthreads();
        #pragma unroll 4
        for (int k = 0; k < 128; k++) {
            float xv = sx[w][kc + k];
            y0 += xv * sWg[k][lane];
            y1 += xv * sWg[k][lane + 32];
        }
        __syncthreads();
    }
    y0 = y0 > 0.0f ? y0 : 0.0f;
    y1 = y1 > 0.0f ? y1 : 0.0f;

    float p[5];
    #pragma unroll
    for (int c = 0; c < 5; c++)
        p[c] = y0 * sWf[lane * 5 + c] + y1 * sWf[(lane + 32) * 5 + c];
    #pragma unroll
    for (int o = 16; o > 0; o >>= 1) {
        #pragma unroll
        for (int c = 0; c < 5; c++)
            p[c] += __shfl_xor_sync(0xffffffffu, p[c], o);
    }
    if (lane == 0) {
        #pragma unroll
        for (int c = 0; c < 5; c++)
            out[node * 5 + c] = p[c] + bf[c];
    }
}

// ---------------- host orchestration ------------------------------------------
extern "C" void kernel_launch(void* const* d_in, const int* in_sizes, int n_in,
                              void* d_out, int out_size) {
    const float* z     = (const float*)d_in[0];
    const int*   ei    = (const int*)d_in[1];
    const int*   batch = (const int*)d_in[2];
    int base = (in_sizes[3] == 1) ? 4 : 3;
    const float* W0  = (const float*)d_in[base + 0];
    const float* b0  = (const float*)d_in[base + 1];
    const float* W1  = (const float*)d_in[base + 2];
    const float* as1 = (const float*)d_in[base + 3];
    const float* ad1 = (const float*)d_in[base + 4];
    const float* bb1 = (const float*)d_in[base + 5];
    const float* W2  = (const float*)d_in[base + 6];
    const float* as2 = (const float*)d_in[base + 7];
    const float* ad2 = (const float*)d_in[base + 8];
    const float* bb2 = (const float*)d_in[base + 9];
    const float* W3  = (const float*)d_in[base + 10];
    const float* as3 = (const float*)d_in[base + 11];
    const float* ad3 = (const float*)d_in[base + 12];
    const float* bb3 = (const float*)d_in[base + 13];
    const float* Wg  = (const float*)d_in[base + 14];
    const float* bg  = (const float*)d_in[base + 15];
    const float* Wf  = (const float*)d_in[base + 16];
    const float* bf  = (const float*)d_in[base + 17];

    const int* srcArr = ei;
    const int* dstArr = ei + NEDGE;

    float *bufA, *bufB, *aS, *aD, *exB, *pgB;
    int *startsB, *degB, *rowptrB, *cursorB, *csrcB;
    cudaGetSymbolAddress((void**)&bufA, g_bufA);
    cudaGetSymbolAddress((void**)&bufB, g_bufB);
    cudaGetSymbolAddress((void**)&aS, g_as);
    cudaGetSymbolAddress((void**)&aD, g_ad);
    cudaGetSymbolAddress((void**)&exB, g_ex);
    cudaGetSymbolAddress((void**)&pgB, g_pg);
    cudaGetSymbolAddress((void**)&startsB, g_starts);
    cudaGetSymbolAddress((void**)&degB, g_deg);
    cudaGetSymbolAddress((void**)&rowptrB, g_rowptr);
    cudaGetSymbolAddress((void**)&cursorB, g_cursor);
    cudaGetSymbolAddress((void**)&csrcB, g_csrc);

    dim3 gemmGrid(NNODE / 128, 2);

    // 1: prologue (x0pg | starts | hist into pre-zeroed deg)
    k_pro<<<NGRAPH + NBLK + EBLK, 256>>>(z, W0, b0, W1, pgB, batch, startsB,
                                         degB, dstArr);
    // 2: CSR rowptr + self-loop fill (+1 per node)
    k_fill2<<<NBLK, 256>>>(degB, rowptrB, cursorB, csrcB);
    // 3: h1+attn | scatter | deg re-zero for next replay
    k_mid<<<WBLK + EBLK + NBLK, 256>>>(pgB, W1, batch, startsB, as1, ad1, bufB,
                                       aS, aD, srcArr, dstArr, cursorB, csrcB,
                                       degB);
    // 4: aggregate layer 1
    k_aggregate<<<WBLK, 256>>>(rowptrB, csrcB, bufB, aS, aD, bb1, exB, bufA);
    // 5-6: layer 2
    k_gemm_attn<<<gemmGrid, 256>>>(bufA, W2, as2, ad2, bufB, aS, aD);
    k_aggregate<<<WBLK, 256>>>(rowptrB, csrcB, bufB, aS, aD, bb2, exB, bufA);
    // 7: layer 3 GEMM
    k_gemm_attn<<<gemmGrid, 256>>>(bufA, W3, as3, ad3, bufB, aS, aD);
    // 8: layer 3 aggregate fused with dec_geo + fc_geo
    k_agg_final<<<WBLK, 256>>>(rowptrB, csrcB, bufB, aS, aD, bb3, exB,
                               Wg, bg, Wf, bf, (float*)d_out);
}